// round 4
// baseline (speedup 1.0000x reference)
#include <cuda_runtime.h>
#include <math.h>

// ---------------------------------------------------------------------------
// SpatialLinearAttention, fp32 baseline with f32x2 packed-FMA GEMMs.
//
// Pipeline (all fp32, deterministic):
//   1) gemm256 x3 : Pq = X@Wq, Pk = X@Wk, Pv = X@Wv          (X: [131072,256])
//   2) qsoftmax   : softmax over each 32-col head group of Pq rows (in place)
//   3) kstat_part / kstat_merge : per-(bf, col) max & sum(exp) over n=4096
//   4) ctx_w2     : per (bf,head): C = softmax(K)^T V (32x32), W2 = C @ Wo_h
//   5) gemm256    : out = Pq @ W2[bf]   (batched B), written straight to d_out
// ---------------------------------------------------------------------------

typedef unsigned long long ull;

#define BFU   32          // b*f
#define NSPA  4096        // h*w
#define CCH   256         // channels == hD
#define HEADS 8
#define DH    32
#define MROWS (BFU*NSPA)  // 131072

// ------------------------------- scratch ----------------------------------
__device__ __align__(128) float g_Pq[(size_t)MROWS * CCH];
__device__ __align__(128) float g_Pk[(size_t)MROWS * CCH];
__device__ __align__(128) float g_Pv[(size_t)MROWS * CCH];
__device__ __align__(128) float g_pmax[BFU * 16 * CCH];
__device__ __align__(128) float g_psum[BFU * 16 * CCH];
__device__ __align__(128) float g_cmax[BFU * CCH];
__device__ __align__(128) float g_cinv[BFU * CCH];
__device__ __align__(128) float g_W2[(size_t)BFU * CCH * CCH];

// --------------------------- f32x2 helpers --------------------------------
__device__ __forceinline__ ull pack2(float x, float y) {
    ull r;
    asm("mov.b64 %0, {%1, %2};" : "=l"(r) : "f"(x), "f"(y));
    return r;
}
__device__ __forceinline__ void unpack2(ull v, float& x, float& y) {
    asm("mov.b64 {%0, %1}, %2;" : "=f"(x), "=f"(y) : "l"(v));
}
__device__ __forceinline__ void fma2(ull& c, ull a, ull b) {
    asm("fma.rn.f32x2 %0, %1, %2, %0;" : "+l"(c) : "l"(a), "l"(b));
}

// ------------------------------- GEMM -------------------------------------
// C[M,256] = A[M,256] @ B[256,256], row-major everywhere.
// Tile 128x128 per CTA, 256 threads, 8x8 micro-tile per thread, K-chunks of 16.
// If batchB != 0, B is indexed per 4096-row batch: B += (row0/4096)*256*256.
__global__ void __launch_bounds__(256) gemm256(
    const float* __restrict__ A, const float* __restrict__ B,
    float* __restrict__ C, int batchB)
{
    __shared__ float As[16 * 132];   // [k][m], padded row (132) keeps 16B align
    __shared__ float Bs[16 * 128];   // [k][n]

    const int row0 = blockIdx.x * 128;
    const int col0 = blockIdx.y * 128;
    if (batchB) B += (size_t)(row0 >> 12) * (256 * 256);

    const int tid = threadIdx.x;
    const int tx = tid & 15, ty = tid >> 4;
    const int tx4 = tx * 4, ty4 = ty * 4;

    // global-load assignments (2 float4 each for A and B tiles)
    const int ar0 = tid >> 2,           ak0 = (tid & 3) * 4;
    const int ar1 = (tid + 256) >> 2,   ak1 = ((tid + 256) & 3) * 4;
    const int bk0 = tid >> 5,           bn0 = (tid & 31) * 4;
    const int bk1 = (tid + 256) >> 5,   bn1 = ((tid + 256) & 31) * 4;

    const float* Aab0 = A + (size_t)(row0 + ar0) * 256 + ak0;
    const float* Aab1 = A + (size_t)(row0 + ar1) * 256 + ak1;
    const float* Bb0  = B + (size_t)bk0 * 256 + col0 + bn0;
    const float* Bb1  = B + (size_t)bk1 * 256 + col0 + bn1;

    float4 pa0 = *(const float4*)(Aab0);
    float4 pa1 = *(const float4*)(Aab1);
    float4 pb0 = *(const float4*)(Bb0);
    float4 pb1 = *(const float4*)(Bb1);

    ull acc[8][4];
#pragma unroll
    for (int i = 0; i < 8; i++)
#pragma unroll
        for (int j = 0; j < 4; j++) acc[i][j] = 0ull;

    for (int kt = 0; kt < 16; ++kt) {
        // stage to smem (A transposed)
        As[(ak0 + 0) * 132 + ar0] = pa0.x;
        As[(ak0 + 1) * 132 + ar0] = pa0.y;
        As[(ak0 + 2) * 132 + ar0] = pa0.z;
        As[(ak0 + 3) * 132 + ar0] = pa0.w;
        As[(ak1 + 0) * 132 + ar1] = pa1.x;
        As[(ak1 + 1) * 132 + ar1] = pa1.y;
        As[(ak1 + 2) * 132 + ar1] = pa1.z;
        As[(ak1 + 3) * 132 + ar1] = pa1.w;
        *(float4*)&Bs[bk0 * 128 + bn0] = pb0;
        *(float4*)&Bs[bk1 * 128 + bn1] = pb1;
        __syncthreads();

        if (kt < 15) {  // prefetch next K-chunk while computing
            const int ko = (kt + 1) * 16;
            pa0 = *(const float4*)(Aab0 + ko);
            pa1 = *(const float4*)(Aab1 + ko);
            pb0 = *(const float4*)(Bb0 + (size_t)ko * 256);
            pb1 = *(const float4*)(Bb1 + (size_t)ko * 256);
        }

#pragma unroll
        for (int k = 0; k < 16; k++) {
            const float4 a0 = *(const float4*)&As[k * 132 + ty4];
            const float4 a1 = *(const float4*)&As[k * 132 + 64 + ty4];
            const float4 b0 = *(const float4*)&Bs[k * 128 + tx4];
            const float4 b1 = *(const float4*)&Bs[k * 128 + 64 + tx4];
            const ull bp0 = pack2(b0.x, b0.y), bp1 = pack2(b0.z, b0.w);
            const ull bp2 = pack2(b1.x, b1.y), bp3 = pack2(b1.z, b1.w);
            const float av[8] = {a0.x, a0.y, a0.z, a0.w, a1.x, a1.y, a1.z, a1.w};
#pragma unroll
            for (int i = 0; i < 8; i++) {
                const ull ad = pack2(av[i], av[i]);
                fma2(acc[i][0], ad, bp0);
                fma2(acc[i][1], ad, bp1);
                fma2(acc[i][2], ad, bp2);
                fma2(acc[i][3], ad, bp3);
            }
        }
        __syncthreads();
    }

    // writeback: rows {ty4+i, 64+ty4+i}, cols {col0+tx4.., col0+64+tx4..}
#pragma unroll
    for (int i = 0; i < 8; i++) {
        const int grow = row0 + ((i < 4) ? (ty4 + i) : (64 + ty4 + i - 4));
        float4 o0, o1;
        unpack2(acc[i][0], o0.x, o0.y);
        unpack2(acc[i][1], o0.z, o0.w);
        unpack2(acc[i][2], o1.x, o1.y);
        unpack2(acc[i][3], o1.z, o1.w);
        *(float4*)&C[(size_t)grow * 256 + col0 + tx4]      = o0;
        *(float4*)&C[(size_t)grow * 256 + col0 + 64 + tx4] = o1;
    }
}

// ----------------------- q softmax over D groups ---------------------------
// Pq rows: each contiguous 32-col group (one head) gets a softmax. One warp
// per group; array is exactly (num_groups * 32) floats, so gid*32+lane maps 1:1.
__global__ void __launch_bounds__(256) qsoftmax_kernel(float* __restrict__ Pq)
{
    const int warp = threadIdx.x >> 5, lane = threadIdx.x & 31;
    const size_t gid = (size_t)blockIdx.x * 8 + warp;
    const size_t off = gid * 32 + lane;
    float v = Pq[off];
    float m = v;
#pragma unroll
    for (int o = 16; o; o >>= 1) m = fmaxf(m, __shfl_xor_sync(0xffffffffu, m, o));
    float e = __expf(v - m);
    float s = e;
#pragma unroll
    for (int o = 16; o; o >>= 1) s += __shfl_xor_sync(0xffffffffu, s, o);
    Pq[off] = e / s;
}

// -------------------- k column softmax statistics --------------------------
// Pass 1: per (bf, 256-row chunk, col): max and sum(exp(x-max)).
__global__ void __launch_bounds__(256) kstat_part(
    const float* __restrict__ Pk, float* __restrict__ pmax, float* __restrict__ psum)
{
    const int bf = blockIdx.x, ch = blockIdx.y, t = threadIdx.x;
    const float* p = Pk + ((size_t)bf * NSPA + ch * 256) * 256 + t;
    float m = -1e30f;
#pragma unroll 8
    for (int r = 0; r < 256; r++) m = fmaxf(m, p[(size_t)r * 256]);
    float s = 0.f;
#pragma unroll 8
    for (int r = 0; r < 256; r++) s += __expf(p[(size_t)r * 256] - m);
    const int o = (bf * 16 + ch) * 256 + t;
    pmax[o] = m;
    psum[o] = s;
}

// Pass 2: merge the 16 chunk partials per (bf, col).
__global__ void __launch_bounds__(256) kstat_merge(
    const float* __restrict__ pmax, const float* __restrict__ psum,
    float* __restrict__ cmax, float* __restrict__ cinv)
{
    const int bf = blockIdx.x, t = threadIdx.x;
    float m = -1e30f;
#pragma unroll
    for (int ch = 0; ch < 16; ch++) m = fmaxf(m, pmax[(bf * 16 + ch) * 256 + t]);
    float s = 0.f;
#pragma unroll
    for (int ch = 0; ch < 16; ch++) {
        const int o = (bf * 16 + ch) * 256 + t;
        s += psum[o] * __expf(pmax[o] - m);
    }
    cmax[bf * 256 + t] = m;
    cinv[bf * 256 + t] = 1.0f / s;
}

// -------------------- context (32x32) + W2 fold ----------------------------
// Per (bf, head): C[d][e] = inv[d] * sum_n exp(Pk[n,h32+d]-max[d]) * Pv[n,h32+e]
// then W2[bf][h32+d][c] = sum_e C[d][e] * Wo[h32+e][c].
__global__ void __launch_bounds__(256) ctx_w2_kernel(
    const float* __restrict__ Pk, const float* __restrict__ Pv,
    const float* __restrict__ cmax, const float* __restrict__ cinv,
    const float* __restrict__ Wo, float* __restrict__ W2)
{
    __shared__ float sk[64 * 32];
    __shared__ float sv[64 * 32];
    __shared__ float sC[32 * 32];
    __shared__ float scmax[32];

    const int bf = blockIdx.x, h = blockIdx.y;
    const int t = threadIdx.x;
    const int d = t & 31, eg = t >> 5, e0 = eg * 4;

    if (t < 32) scmax[t] = cmax[bf * 256 + h * 32 + t];
    __syncthreads();

    float acc0 = 0.f, acc1 = 0.f, acc2 = 0.f, acc3 = 0.f;
    const float* pkb = Pk + (size_t)bf * NSPA * 256 + h * 32;
    const float* pvb = Pv + (size_t)bf * NSPA * 256 + h * 32;

    for (int n0 = 0; n0 < NSPA; n0 += 64) {
#pragma unroll
        for (int i = 0; i < 2; i++) {
            const int idx = t + i * 256;          // 0..511
            const int rr = idx >> 3, c4 = (idx & 7) * 4;
            const float4 kv = *(const float4*)(pkb + (size_t)(n0 + rr) * 256 + c4);
            const float4 vv = *(const float4*)(pvb + (size_t)(n0 + rr) * 256 + c4);
            float4 ke;
            ke.x = __expf(kv.x - scmax[c4 + 0]);
            ke.y = __expf(kv.y - scmax[c4 + 1]);
            ke.z = __expf(kv.z - scmax[c4 + 2]);
            ke.w = __expf(kv.w - scmax[c4 + 3]);
            *(float4*)&sk[rr * 32 + c4] = ke;
            *(float4*)&sv[rr * 32 + c4] = vv;
        }
        __syncthreads();
#pragma unroll 8
        for (int nn = 0; nn < 64; nn++) {
            const float kd = sk[nn * 32 + d];
            const float4 v4 = *(const float4*)&sv[nn * 32 + e0];
            acc0 += kd * v4.x;
            acc1 += kd * v4.y;
            acc2 += kd * v4.z;
            acc3 += kd * v4.w;
        }
        __syncthreads();
    }

    const float inv = cinv[bf * 256 + h * 32 + d];
    sC[d * 32 + e0 + 0] = acc0 * inv;
    sC[d * 32 + e0 + 1] = acc1 * inv;
    sC[d * 32 + e0 + 2] = acc2 * inv;
    sC[d * 32 + e0 + 3] = acc3 * inv;
    __syncthreads();

    // W2 fold: thread t owns output column c = t.
    float wo[32];
#pragma unroll
    for (int e = 0; e < 32; e++) wo[e] = Wo[(size_t)(h * 32 + e) * 256 + t];
    float* w2p = W2 + ((size_t)bf * 256 + h * 32) * 256 + t;
    for (int d2 = 0; d2 < 32; d2++) {
        float s = 0.f;
#pragma unroll
        for (int e = 0; e < 32; e++) s += sC[d2 * 32 + e] * wo[e];
        w2p[(size_t)d2 * 256] = s;
    }
}

// ------------------------------ launcher -----------------------------------
extern "C" void kernel_launch(void* const* d_in, const int* in_sizes, int n_in,
                              void* d_out, int out_size)
{
    (void)in_sizes; (void)n_in; (void)out_size;
    const float* x  = (const float*)d_in[0];
    const float* Wq = (const float*)d_in[1];
    const float* Wk = (const float*)d_in[2];
    const float* Wv = (const float*)d_in[3];
    const float* Wo = (const float*)d_in[4];
    float* out = (float*)d_out;

    float *Pq, *Pk, *Pv, *pmax, *psum, *cmax, *cinv, *W2;
    cudaGetSymbolAddress((void**)&Pq,   g_Pq);
    cudaGetSymbolAddress((void**)&Pk,   g_Pk);
    cudaGetSymbolAddress((void**)&Pv,   g_Pv);
    cudaGetSymbolAddress((void**)&pmax, g_pmax);
    cudaGetSymbolAddress((void**)&psum, g_psum);
    cudaGetSymbolAddress((void**)&cmax, g_cmax);
    cudaGetSymbolAddress((void**)&cinv, g_cinv);
    cudaGetSymbolAddress((void**)&W2,   g_W2);

    const dim3 gg(MROWS / 128, 2);

    gemm256<<<gg, 256>>>(x, Wq, Pq, 0);
    gemm256<<<gg, 256>>>(x, Wk, Pk, 0);
    gemm256<<<gg, 256>>>(x, Wv, Pv, 0);

    qsoftmax_kernel<<<MROWS, 256>>>(Pq);

    kstat_part<<<dim3(BFU, 16), 256>>>(Pk, pmax, psum);
    kstat_merge<<<BFU, 256>>>(pmax, psum, cmax, cinv);

    ctx_w2_kernel<<<dim3(BFU, HEADS), 256>>>(Pk, Pv, cmax, cinv, Wo, W2);

    gemm256<<<gg, 256>>>(Pq, W2, out, 1);
}

// round 6
// speedup vs baseline: 1.4966x; 1.4966x over previous
#include <cuda_runtime.h>
#include <cuda_bf16.h>
#include <cstdint>
#include <math.h>

// ---------------------------------------------------------------------------
// SpatialLinearAttention — mma.sync (base-target HMMA) bf16 hi/lo split GEMMs.
// tcgen05 is unavailable: harness PTX target is compute_100 (no 'a' features).
//
//   1) tsplit x3 : Wq/Wk/Wv -> transposed [n][k] bf16 hi/lo
//   2) mma_gemm  : Pq/Pk/Pv = X @ W   (grid.x = weight; q-softmax fused)
//   3) kstat_*   : column softmax stats for Pk
//   4) ctx_w2    : per (bf,head) 32x32 context + fold with Wo -> W2 (fp32)
//   5) tsplit    : W2 -> transposed bf16 hi/lo (batched 32)
//   6) mma_gemm  : out = Pq @ W2[bf]
// ---------------------------------------------------------------------------

#define BFU   32
#define NSPA  4096
#define HEADS 8
#define MROWS (BFU*NSPA)   // 131072

// ------------------------------- scratch ----------------------------------
__device__ __align__(128) float g_Pq[(size_t)MROWS * 256];
__device__ __align__(128) float g_Pk[(size_t)MROWS * 256];
__device__ __align__(128) float g_Pv[(size_t)MROWS * 256];
__device__ __align__(128) float g_pmax[BFU * 16 * 256];
__device__ __align__(128) float g_psum[BFU * 16 * 256];
__device__ __align__(128) float g_cmax[BFU * 256];
__device__ __align__(128) float g_cinv[BFU * 256];
__device__ __align__(128) float g_W2[(size_t)BFU * 256 * 256];
__device__ __align__(128) __nv_bfloat16 g_Wt_hi[3 * 65536];
__device__ __align__(128) __nv_bfloat16 g_Wt_lo[3 * 65536];
__device__ __align__(128) __nv_bfloat16 g_W2t_hi[(size_t)BFU * 65536];
__device__ __align__(128) __nv_bfloat16 g_W2t_lo[(size_t)BFU * 65536];

// ----------------------------- helpers -------------------------------------
__device__ __forceinline__ uint32_t smem_u32(const void* p) {
    uint32_t a;
    asm("{ .reg .u64 t; cvta.to.shared.u64 t, %1; cvt.u32.u64 %0, t; }"
        : "=r"(a) : "l"(p));
    return a;
}

__device__ __forceinline__ void split2(float x, float y,
                                       unsigned int& h, unsigned int& l) {
    __nv_bfloat16 hx = __float2bfloat16(x), hy = __float2bfloat16(y);
    float rx = x - __bfloat162float(hx), ry = y - __bfloat162float(hy);
    h = (uint32_t)__bfloat16_as_ushort(hx) |
        ((uint32_t)__bfloat16_as_ushort(hy) << 16);
    l = (uint32_t)__bfloat16_as_ushort(__float2bfloat16(rx)) |
        ((uint32_t)__bfloat16_as_ushort(__float2bfloat16(ry)) << 16);
}

#define LDSM4(R0, R1, R2, R3, ADDR) \
    asm volatile("ldmatrix.sync.aligned.m8n8.x4.shared.b16 {%0,%1,%2,%3}, [%4];" \
        : "=r"(R0), "=r"(R1), "=r"(R2), "=r"(R3) : "r"(ADDR))

#define MMA16816(D, Af, Bf) \
    asm volatile("mma.sync.aligned.m16n8k16.row.col.f32.bf16.bf16.f32 " \
        "{%0,%1,%2,%3}, {%4,%5,%6,%7}, {%8,%9}, {%0,%1,%2,%3};" \
        : "+f"((D)[0]), "+f"((D)[1]), "+f"((D)[2]), "+f"((D)[3]) \
        : "r"((Af)[0]), "r"((Af)[1]), "r"((Af)[2]), "r"((Af)[3]), \
          "r"((Bf)[0]), "r"((Bf)[1]))

// --------------------- weight transpose + bf16 split -----------------------
// dst[z][n][k] (bf16 hi/lo) = src[z][k][n] (fp32). grid (8,8,batch), block (32,8).
__global__ void __launch_bounds__(256) tsplit(
    const float* __restrict__ src,
    __nv_bfloat16* __restrict__ dhi, __nv_bfloat16* __restrict__ dlo)
{
    __shared__ float t[32][33];
    const size_t base = (size_t)blockIdx.z * 65536;
    const int tx = threadIdx.x, ty = threadIdx.y;
    const int xs = blockIdx.x * 32 + tx;
    const int ys = blockIdx.y * 32;
#pragma unroll
    for (int j = 0; j < 32; j += 8)
        t[ty + j][tx] = src[base + (size_t)(ys + ty + j) * 256 + xs];
    __syncthreads();
    const int xo = blockIdx.y * 32 + tx;
    const int yo = blockIdx.x * 32;
#pragma unroll
    for (int j = 0; j < 32; j += 8) {
        const float v = t[tx][ty + j];
        const __nv_bfloat16 h = __float2bfloat16(v);
        const float r = v - __bfloat162float(h);
        dhi[base + (size_t)(yo + ty + j) * 256 + xo] = h;
        dlo[base + (size_t)(yo + ty + j) * 256 + xo] = __float2bfloat16(r);
    }
}

// ----------------------------- mma.sync GEMM -------------------------------
// C[128-row block, 128-col block] = A[.,256] @ B (bf16 hi/lo, [n][k] layout).
// grid (W, 2048): blockIdx.y = (m-block<<1) | col-block. 3-term split in fp32.
// smax: fused per-32-col head-group softmax (only weight slab w==0).
#define PITCH 40                 // bf16 elems per smem row (80 B, swizzle-free)
#define SM_AH 0
#define SM_AL 10240
#define SM_BH 20480
#define SM_BL 30720

__global__ void __launch_bounds__(256, 1) mma_gemm(
    const float* __restrict__ A,
    const __nv_bfloat16* __restrict__ Bhi, const __nv_bfloat16* __restrict__ Blo,
    float* __restrict__ C0, float* __restrict__ C1, float* __restrict__ C2,
    int batchB, int smax)
{
    __shared__ __align__(16) unsigned char sm[40960];
    const uint32_t sb = smem_u32(sm);
    const int tid = threadIdx.x, lane = tid & 31, wid = tid >> 5;
    const int wm = wid & 1, wn = wid >> 1;      // warp grid 2(m) x 4(n)
    const int w = blockIdx.x;
    const int mb = blockIdx.y >> 1, cb = blockIdx.y & 1;
    const int row0 = mb * 128, col0 = cb * 128;

    size_t boff = (size_t)w * 65536;
    if (batchB) boff += (size_t)(mb >> 5) * 65536;
    const __nv_bfloat16* BH = Bhi + boff + (size_t)col0 * 256;
    const __nv_bfloat16* BL = Blo + boff + (size_t)col0 * 256;
    float* C = (w == 0) ? C0 : ((w == 1) ? C1 : C2);
    const int dosm = smax && (w == 0);
    const float* Ab = A + (size_t)row0 * 256;

    // staging assignments
    const int am0 = tid >> 3, ak0 = (tid & 7) * 4;   // A: +32 rows per i
    const int bn0 = tid >> 2, bk0 = (tid & 3) * 8;   // B: +64 rows per i

    // ldmatrix lane addressing (bytes)
    const uint32_t a_base = sb + SM_AH +
        (uint32_t)(((wm * 64 + (lane & 15)) * PITCH + (lane >> 4) * 8) * 2);
    const int bn_l = (lane & 7) + ((lane >> 4) & 1) * 8;
    const int bk_l = ((lane >> 3) & 1) * 8;
    const uint32_t b_base = sb + SM_BH +
        (uint32_t)(((wn * 32 + bn_l) * PITCH + bk_l) * 2);

    float acc[4][4][4];
#pragma unroll
    for (int i = 0; i < 4; i++)
#pragma unroll
        for (int j = 0; j < 4; j++)
#pragma unroll
            for (int r = 0; r < 4; r++) acc[i][j][r] = 0.f;

    float4 va[4];
    uint4 vbh[2], vbl[2];

    auto load_chunk = [&](int k0) {
#pragma unroll
        for (int i = 0; i < 4; i++)
            va[i] = *(const float4*)(Ab + (size_t)(am0 + i * 32) * 256 + k0 + ak0);
#pragma unroll
        for (int i = 0; i < 2; i++) {
            vbh[i] = *(const uint4*)(BH + (size_t)(bn0 + i * 64) * 256 + k0 + bk0);
            vbl[i] = *(const uint4*)(BL + (size_t)(bn0 + i * 64) * 256 + k0 + bk0);
        }
    };
    auto store_chunk = [&]() {
#pragma unroll
        for (int i = 0; i < 4; i++) {
            uint2 h, l;
            split2(va[i].x, va[i].y, h.x, l.x);
            split2(va[i].z, va[i].w, h.y, l.y);
            const int ob = (am0 + i * 32) * 80 + ak0 * 2;
            *(uint2*)(sm + SM_AH + ob) = h;
            *(uint2*)(sm + SM_AL + ob) = l;
        }
#pragma unroll
        for (int i = 0; i < 2; i++) {
            const int ob = (bn0 + i * 64) * 80 + bk0 * 2;
            *(uint4*)(sm + SM_BH + ob) = vbh[i];
            *(uint4*)(sm + SM_BL + ob) = vbl[i];
        }
    };

    load_chunk(0);
    store_chunk();

    for (int kc = 0; kc < 8; kc++) {
        __syncthreads();
        if (kc < 7) load_chunk((kc + 1) * 32);   // LDGs overlap the compute below

#pragma unroll
        for (int ks = 0; ks < 2; ks++) {
            const uint32_t off = ks * 32;        // +16 k elems = 32 bytes
            uint32_t ah[4][4], al[4][4], bh[4][2], bl[4][2];
#pragma unroll
            for (int mt = 0; mt < 4; mt++) {
                LDSM4(ah[mt][0], ah[mt][1], ah[mt][2], ah[mt][3],
                      a_base + mt * 1280 + off);
                LDSM4(al[mt][0], al[mt][1], al[mt][2], al[mt][3],
                      a_base + 10240 + mt * 1280 + off);
            }
            LDSM4(bh[0][0], bh[0][1], bh[1][0], bh[1][1], b_base + off);
            LDSM4(bh[2][0], bh[2][1], bh[3][0], bh[3][1], b_base + 1280 + off);
            LDSM4(bl[0][0], bl[0][1], bl[1][0], bl[1][1], b_base + 10240 + off);
            LDSM4(bl[2][0], bl[2][1], bl[3][0], bl[3][1], b_base + 11520 + off);
#pragma unroll
            for (int mt = 0; mt < 4; mt++)
#pragma unroll
                for (int nt = 0; nt < 4; nt++) {
                    MMA16816(acc[mt][nt], ah[mt], bh[nt]);
                    MMA16816(acc[mt][nt], ah[mt], bl[nt]);
                    MMA16816(acc[mt][nt], al[mt], bh[nt]);
                }
        }
        __syncthreads();
        if (kc < 7) store_chunk();
    }

    // ---- epilogue: optional fused head-group softmax, then direct stores ----
    if (dosm) {
#pragma unroll
        for (int mt = 0; mt < 4; mt++)
#pragma unroll
            for (int h = 0; h < 2; h++) {
                float mx = -1e30f;
#pragma unroll
                for (int nt = 0; nt < 4; nt++)
                    mx = fmaxf(mx, fmaxf(acc[mt][nt][2*h], acc[mt][nt][2*h+1]));
                mx = fmaxf(mx, __shfl_xor_sync(0xffffffffu, mx, 1));
                mx = fmaxf(mx, __shfl_xor_sync(0xffffffffu, mx, 2));
                float s = 0.f;
#pragma unroll
                for (int nt = 0; nt < 4; nt++) {
                    acc[mt][nt][2*h]   = __expf(acc[mt][nt][2*h]   - mx);
                    acc[mt][nt][2*h+1] = __expf(acc[mt][nt][2*h+1] - mx);
                    s += acc[mt][nt][2*h] + acc[mt][nt][2*h+1];
                }
                s += __shfl_xor_sync(0xffffffffu, s, 1);
                s += __shfl_xor_sync(0xffffffffu, s, 2);
                const float inv = 1.0f / s;
#pragma unroll
                for (int nt = 0; nt < 4; nt++) {
                    acc[mt][nt][2*h]   *= inv;
                    acc[mt][nt][2*h+1] *= inv;
                }
            }
    }

    const int r0 = row0 + wm * 64 + (lane >> 2);
    const int c0 = col0 + wn * 32 + (lane & 3) * 2;
#pragma unroll
    for (int mt = 0; mt < 4; mt++)
#pragma unroll
        for (int nt = 0; nt < 4; nt++) {
            const int r = r0 + mt * 16, c = c0 + nt * 8;
            *(float2*)&C[(size_t)r * 256 + c] =
                make_float2(acc[mt][nt][0], acc[mt][nt][1]);
            *(float2*)&C[(size_t)(r + 8) * 256 + c] =
                make_float2(acc[mt][nt][2], acc[mt][nt][3]);
        }
}

// -------------------- k column softmax statistics (known-good) -------------
__global__ void __launch_bounds__(256) kstat_part(
    const float* __restrict__ Pk, float* __restrict__ pmax, float* __restrict__ psum)
{
    const int bf = blockIdx.x, ch = blockIdx.y, t = threadIdx.x;
    const float* p = Pk + ((size_t)bf * NSPA + ch * 256) * 256 + t;
    float m = -1e30f;
#pragma unroll 8
    for (int r = 0; r < 256; r++) m = fmaxf(m, p[(size_t)r * 256]);
    float s = 0.f;
#pragma unroll 8
    for (int r = 0; r < 256; r++) s += __expf(p[(size_t)r * 256] - m);
    const int o = (bf * 16 + ch) * 256 + t;
    pmax[o] = m;
    psum[o] = s;
}

__global__ void __launch_bounds__(256) kstat_merge(
    const float* __restrict__ pmax, const float* __restrict__ psum,
    float* __restrict__ cmax, float* __restrict__ cinv)
{
    const int bf = blockIdx.x, t = threadIdx.x;
    float m = -1e30f;
#pragma unroll
    for (int ch = 0; ch < 16; ch++) m = fmaxf(m, pmax[(bf * 16 + ch) * 256 + t]);
    float s = 0.f;
#pragma unroll
    for (int ch = 0; ch < 16; ch++) {
        const int o = (bf * 16 + ch) * 256 + t;
        s += psum[o] * __expf(pmax[o] - m);
    }
    cmax[bf * 256 + t] = m;
    cinv[bf * 256 + t] = 1.0f / s;
}

// -------------------- context (32x32) + W2 fold (known-good) ---------------
__global__ void __launch_bounds__(256) ctx_w2_kernel(
    const float* __restrict__ Pk, const float* __restrict__ Pv,
    const float* __restrict__ cmax, const float* __restrict__ cinv,
    const float* __restrict__ Wo, float* __restrict__ W2)
{
    __shared__ float sk[64 * 32];
    __shared__ float sv[64 * 32];
    __shared__ float sC[32 * 32];
    __shared__ float scmax[32];

    const int bf = blockIdx.x, h = blockIdx.y;
    const int t = threadIdx.x;
    const int d = t & 31, eg = t >> 5, e0 = eg * 4;

    if (t < 32) scmax[t] = cmax[bf * 256 + h * 32 + t];
    __syncthreads();

    float acc0 = 0.f, acc1 = 0.f, acc2 = 0.f, acc3 = 0.f;
    const float* pkb = Pk + (size_t)bf * NSPA * 256 + h * 32;
    const float* pvb = Pv + (size_t)bf * NSPA * 256 + h * 32;

    for (int n0 = 0; n0 < NSPA; n0 += 64) {
#pragma unroll
        for (int i = 0; i < 2; i++) {
            const int idx = t + i * 256;
            const int rr = idx >> 3, c4 = (idx & 7) * 4;
            const float4 kv = *(const float4*)(pkb + (size_t)(n0 + rr) * 256 + c4);
            const float4 vv = *(const float4*)(pvb + (size_t)(n0 + rr) * 256 + c4);
            float4 ke;
            ke.x = __expf(kv.x - scmax[c4 + 0]);
            ke.y = __expf(kv.y - scmax[c4 + 1]);
            ke.z = __expf(kv.z - scmax[c4 + 2]);
            ke.w = __expf(kv.w - scmax[c4 + 3]);
            *(float4*)&sk[rr * 32 + c4] = ke;
            *(float4*)&sv[rr * 32 + c4] = vv;
        }
        __syncthreads();
#pragma unroll 8
        for (int nn = 0; nn < 64; nn++) {
            const float kd = sk[nn * 32 + d];
            const float4 v4 = *(const float4*)&sv[nn * 32 + e0];
            acc0 += kd * v4.x;
            acc1 += kd * v4.y;
            acc2 += kd * v4.z;
            acc3 += kd * v4.w;
        }
        __syncthreads();
    }

    const float inv = cinv[bf * 256 + h * 32 + d];
    sC[d * 32 + e0 + 0] = acc0 * inv;
    sC[d * 32 + e0 + 1] = acc1 * inv;
    sC[d * 32 + e0 + 2] = acc2 * inv;
    sC[d * 32 + e0 + 3] = acc3 * inv;
    __syncthreads();

    float wo[32];
#pragma unroll
    for (int e = 0; e < 32; e++) wo[e] = Wo[(size_t)(h * 32 + e) * 256 + t];
    float* w2p = W2 + ((size_t)bf * 256 + h * 32) * 256 + t;
    for (int d2 = 0; d2 < 32; d2++) {
        float s = 0.f;
#pragma unroll
        for (int e = 0; e < 32; e++) s += sC[d2 * 32 + e] * wo[e];
        w2p[(size_t)d2 * 256] = s;
    }
}

// ------------------------------ launcher -----------------------------------
extern "C" void kernel_launch(void* const* d_in, const int* in_sizes, int n_in,
                              void* d_out, int out_size)
{
    (void)in_sizes; (void)n_in; (void)out_size;
    const float* x  = (const float*)d_in[0];
    const float* Wq = (const float*)d_in[1];
    const float* Wk = (const float*)d_in[2];
    const float* Wv = (const float*)d_in[3];
    const float* Wo = (const float*)d_in[4];
    float* out = (float*)d_out;

    float *Pq, *Pk, *Pv, *pmax, *psum, *cmax, *cinv, *W2;
    __nv_bfloat16 *Wth, *Wtl, *W2th, *W2tl;
    cudaGetSymbolAddress((void**)&Pq,   g_Pq);
    cudaGetSymbolAddress((void**)&Pk,   g_Pk);
    cudaGetSymbolAddress((void**)&Pv,   g_Pv);
    cudaGetSymbolAddress((void**)&pmax, g_pmax);
    cudaGetSymbolAddress((void**)&psum, g_psum);
    cudaGetSymbolAddress((void**)&cmax, g_cmax);
    cudaGetSymbolAddress((void**)&cinv, g_cinv);
    cudaGetSymbolAddress((void**)&W2,   g_W2);
    cudaGetSymbolAddress((void**)&Wth,  g_Wt_hi);
    cudaGetSymbolAddress((void**)&Wtl,  g_Wt_lo);
    cudaGetSymbolAddress((void**)&W2th, g_W2t_hi);
    cudaGetSymbolAddress((void**)&W2tl, g_W2t_lo);

    const dim3 tb(32, 8);
    tsplit<<<dim3(8, 8, 1), tb>>>(Wq, Wth,          Wtl);
    tsplit<<<dim3(8, 8, 1), tb>>>(Wk, Wth + 65536,  Wtl + 65536);
    tsplit<<<dim3(8, 8, 1), tb>>>(Wv, Wth + 131072, Wtl + 131072);

    // projections: Pq (softmax fused), Pk, Pv
    mma_gemm<<<dim3(3, MROWS / 64), 256>>>(x, Wth, Wtl, Pq, Pk, Pv, 0, 1);

    kstat_part<<<dim3(BFU, 16), 256>>>(Pk, pmax, psum);
    kstat_merge<<<BFU, 256>>>(pmax, psum, cmax, cinv);
    ctx_w2_kernel<<<dim3(BFU, HEADS), 256>>>(Pk, Pv, cmax, cinv, Wo, W2);

    tsplit<<<dim3(8, 8, BFU), tb>>>(W2, W2th, W2tl);

    // out = Pq @ W2[bf]
    mma_gemm<<<dim3(1, MROWS / 64), 256>>>(Pq, W2th, W2tl, out, out, out, 1, 0);
}

// round 7
// speedup vs baseline: 1.6243x; 1.0854x over previous
#include <cuda_runtime.h>
#include <cuda_bf16.h>
#include <cstdint>
#include <math.h>

// ---------------------------------------------------------------------------
// SpatialLinearAttention — mma.sync bf16 hi/lo split GEMMs, cp.async 3-stage
// pipeline, CTA tile 128x256 (warp tile 64x64).
//
//   0) xsplit    : X fp32 -> Xh/Xl bf16 (row-major)
//   1) tsplit x3 : Wq/Wk/Wv -> transposed [n][k] bf16 hi/lo
//   2) mma_gemm  : Pq/Pk/Pv = X @ W  (w = blockIdx.x; Pq: fused softmax ->
//                  bf16 hi/lo output; Pk/Pv: fp32)
//   3) kstat_*   : column softmax stats for Pk
//   4) ctx_w2    : per (bf,head) 32x32 context + fold with Wo -> W2 (fp32)
//   5) tsplit    : W2 -> transposed bf16 hi/lo (batched 32)
//   6) mma_gemm  : out = Pq @ W2[bf]  (fp32 out)
// ---------------------------------------------------------------------------

#define BFU   32
#define NSPA  4096
#define HEADS 8
#define MROWS (BFU*NSPA)   // 131072

// ------------------------------- scratch ----------------------------------
__device__ __align__(128) float g_Pk[(size_t)MROWS * 256];
__device__ __align__(128) float g_Pv[(size_t)MROWS * 256];
__device__ __align__(128) __nv_bfloat16 g_Xh[(size_t)MROWS * 256];
__device__ __align__(128) __nv_bfloat16 g_Xl[(size_t)MROWS * 256];
__device__ __align__(128) __nv_bfloat16 g_Pqh[(size_t)MROWS * 256];
__device__ __align__(128) __nv_bfloat16 g_Pql[(size_t)MROWS * 256];
__device__ __align__(128) float g_pmax[BFU * 16 * 256];
__device__ __align__(128) float g_psum[BFU * 16 * 256];
__device__ __align__(128) float g_cmax[BFU * 256];
__device__ __align__(128) float g_cinv[BFU * 256];
__device__ __align__(128) float g_W2[(size_t)BFU * 256 * 256];
__device__ __align__(128) __nv_bfloat16 g_Wt_hi[3 * 65536];
__device__ __align__(128) __nv_bfloat16 g_Wt_lo[3 * 65536];
__device__ __align__(128) __nv_bfloat16 g_W2t_hi[(size_t)BFU * 65536];
__device__ __align__(128) __nv_bfloat16 g_W2t_lo[(size_t)BFU * 65536];

// ----------------------------- helpers -------------------------------------
__device__ __forceinline__ uint32_t smem_u32(const void* p) {
    uint32_t a;
    asm("{ .reg .u64 t; cvta.to.shared.u64 t, %1; cvt.u32.u64 %0, t; }"
        : "=r"(a) : "l"(p));
    return a;
}

__device__ __forceinline__ void split2(float x, float y,
                                       unsigned int& h, unsigned int& l) {
    __nv_bfloat16 hx = __float2bfloat16(x), hy = __float2bfloat16(y);
    float rx = x - __bfloat162float(hx), ry = y - __bfloat162float(hy);
    h = (uint32_t)__bfloat16_as_ushort(hx) |
        ((uint32_t)__bfloat16_as_ushort(hy) << 16);
    l = (uint32_t)__bfloat16_as_ushort(__float2bfloat16(rx)) |
        ((uint32_t)__bfloat16_as_ushort(__float2bfloat16(ry)) << 16);
}

#define LDSM4(R0, R1, R2, R3, ADDR) \
    asm volatile("ldmatrix.sync.aligned.m8n8.x4.shared.b16 {%0,%1,%2,%3}, [%4];" \
        : "=r"(R0), "=r"(R1), "=r"(R2), "=r"(R3) : "r"(ADDR))

#define MMA16816(D, Af, Bf) \
    asm volatile("mma.sync.aligned.m16n8k16.row.col.f32.bf16.bf16.f32 " \
        "{%0,%1,%2,%3}, {%4,%5,%6,%7}, {%8,%9}, {%0,%1,%2,%3};" \
        : "+f"((D)[0]), "+f"((D)[1]), "+f"((D)[2]), "+f"((D)[3]) \
        : "r"((Af)[0]), "r"((Af)[1]), "r"((Af)[2]), "r"((Af)[3]), \
          "r"((Bf)[0]), "r"((Bf)[1]))

#define CPA16(DST, SRC) \
    asm volatile("cp.async.cg.shared.global [%0], [%1], 16;" \
        :: "r"(DST), "l"(SRC) : "memory")
#define CP_COMMIT() asm volatile("cp.async.commit_group;" ::: "memory")
#define CP_WAIT1()  asm volatile("cp.async.wait_group 1;" ::: "memory")

// -------------------------- X fp32 -> bf16 hi/lo ---------------------------
__global__ void __launch_bounds__(256) xsplit(
    const float* __restrict__ src,
    __nv_bfloat16* __restrict__ dh, __nv_bfloat16* __restrict__ dl)
{
    const size_t i = ((size_t)blockIdx.x * 256 + threadIdx.x) * 4;
    const float4 v = *(const float4*)(src + i);
    uint2 h, l;
    split2(v.x, v.y, h.x, l.x);
    split2(v.z, v.w, h.y, l.y);
    *(uint2*)(dh + i) = h;
    *(uint2*)(dl + i) = l;
}

// --------------------- weight transpose + bf16 split -----------------------
// dst[z][n][k] (bf16 hi/lo) = src[z][k][n] (fp32). grid (8,8,batch), block (32,8).
__global__ void __launch_bounds__(256) tsplit(
    const float* __restrict__ src,
    __nv_bfloat16* __restrict__ dhi, __nv_bfloat16* __restrict__ dlo)
{
    __shared__ float t[32][33];
    const size_t base = (size_t)blockIdx.z * 65536;
    const int tx = threadIdx.x, ty = threadIdx.y;
    const int xs = blockIdx.x * 32 + tx;
    const int ys = blockIdx.y * 32;
#pragma unroll
    for (int j = 0; j < 32; j += 8)
        t[ty + j][tx] = src[base + (size_t)(ys + ty + j) * 256 + xs];
    __syncthreads();
    const int xo = blockIdx.y * 32 + tx;
    const int yo = blockIdx.x * 32;
#pragma unroll
    for (int j = 0; j < 32; j += 8) {
        const float v = t[tx][ty + j];
        const __nv_bfloat16 h = __float2bfloat16(v);
        const float r = v - __bfloat162float(h);
        dhi[base + (size_t)(yo + ty + j) * 256 + xo] = h;
        dlo[base + (size_t)(yo + ty + j) * 256 + xo] = __float2bfloat16(r);
    }
}

// ----------------------------- mma.sync GEMM -------------------------------
// C[128-row block, 256] = A[.,256] @ B (bf16 hi/lo, [n][k]).
// grid (W, 1024). 3-term split (AhBh + AlBh + AhBl) in fp32 accumulators.
// w==0 && qmode: fused per-32-col head-group softmax, bf16 hi/lo output.
#define PITCH_B 80               // bytes per smem row (40 bf16), conflict-free
#define STG_A   10240            // A-hi bytes per stage (128 rows x 80)
#define STG_B   20480            // B-hi bytes per stage (256 rows x 80)
#define STAGE_BYTES (2*STG_A + 2*STG_B)   // 61440
#define NSTAGE  3
#define SMEM_TOTAL (NSTAGE * STAGE_BYTES) // 184320

__global__ void __launch_bounds__(256, 1) mma_gemm(
    const __nv_bfloat16* __restrict__ Ah, const __nv_bfloat16* __restrict__ Al,
    const __nv_bfloat16* __restrict__ Bhi, const __nv_bfloat16* __restrict__ Blo,
    float* __restrict__ C0, float* __restrict__ C1, float* __restrict__ C2,
    __nv_bfloat16* __restrict__ Ph, __nv_bfloat16* __restrict__ Pl,
    int batchB, int qmode)
{
    extern __shared__ __align__(16) unsigned char sm[];
    const uint32_t sb = smem_u32(sm);
    const int tid = threadIdx.x, lane = tid & 31, wid = tid >> 5;
    const int wm = wid & 1, wn = wid >> 1;      // warp grid 2(m) x 4(n), 64x64
    const int w = blockIdx.x, mb = blockIdx.y;
    const int row0 = mb * 128;

    size_t boff = (size_t)w * 65536;
    if (batchB) boff += (size_t)(mb >> 5) * 65536;
    const __nv_bfloat16* BH = Bhi + boff;
    const __nv_bfloat16* BL = Blo + boff;
    float* C = (w == 0) ? C0 : ((w == 1) ? C1 : C2);
    const int dosm = qmode && (w == 0);

    const __nv_bfloat16* AHg = Ah + (size_t)row0 * 256;
    const __nv_bfloat16* ALg = Al + (size_t)row0 * 256;

    // per-thread cp.async assignments (row, 16B-chunk j within 64B k-slice)
    const int a_r0 = tid >> 2, a_j = (tid & 3) * 8;      // +64 rows per i (2x)
    const int b_r0 = tid >> 2, b_j = (tid & 3) * 8;      // +64 rows per i (4x)

    // ldmatrix lane addressing (byte offsets within a stage)
    const uint32_t a_off =
        (uint32_t)((wm * 64 + (lane & 15)) * PITCH_B + (lane >> 4) * 16);
    const int bn_l = (lane & 7) + ((lane >> 4) & 1) * 8;
    const int bk_l = ((lane >> 3) & 1) * 16;
    const uint32_t b_off = 2 * STG_A +
        (uint32_t)((wn * 64 + bn_l) * PITCH_B + bk_l);

    float acc[4][8][4];
#pragma unroll
    for (int i = 0; i < 4; i++)
#pragma unroll
        for (int j = 0; j < 8; j++)
#pragma unroll
            for (int r = 0; r < 4; r++) acc[i][j][r] = 0.f;

    auto load_stage = [&](int stage, int kc) {
        const uint32_t sd = sb + stage * STAGE_BYTES;
        const int k0 = kc * 32;
#pragma unroll
        for (int i = 0; i < 2; i++) {               // A: 128 rows
            const int r = a_r0 + i * 64;
            const uint32_t d = sd + (uint32_t)(r * PITCH_B) + (a_j * 2);
            const size_t s = (size_t)r * 256 + k0 + a_j;
            CPA16(d,         AHg + s);
            CPA16(d + STG_A, ALg + s);
        }
#pragma unroll
        for (int i = 0; i < 4; i++) {               // B: 256 rows
            const int r = b_r0 + i * 64;
            const uint32_t d = sd + 2 * STG_A + (uint32_t)(r * PITCH_B) + (b_j * 2);
            const size_t s = (size_t)r * 256 + k0 + b_j;
            CPA16(d,         BH + s);
            CPA16(d + STG_B, BL + s);
        }
    };

    load_stage(0, 0); CP_COMMIT();
    load_stage(1, 1); CP_COMMIT();

    for (int kc = 0; kc < 8; kc++) {
        CP_WAIT1();
        __syncthreads();
        const uint32_t st = sb + (kc % 3) * STAGE_BYTES;
        const uint32_t ab = st + a_off, bb = st + b_off;

#pragma unroll
        for (int ks = 0; ks < 2; ks++) {
            const uint32_t off = ks * 32;
            uint32_t ah[4][4], bh[8][2];
#pragma unroll
            for (int mt = 0; mt < 4; mt++)
                LDSM4(ah[mt][0], ah[mt][1], ah[mt][2], ah[mt][3],
                      ab + mt * (16 * PITCH_B) + off);
#pragma unroll
            for (int p = 0; p < 4; p++)
                LDSM4(bh[2*p][0], bh[2*p][1], bh[2*p+1][0], bh[2*p+1][1],
                      bb + p * (16 * PITCH_B) + off);
#pragma unroll
            for (int mt = 0; mt < 4; mt++)
#pragma unroll
                for (int nt = 0; nt < 8; nt++)
                    MMA16816(acc[mt][nt], ah[mt], bh[nt]);
            {   // lo(A) x hi(B)
                uint32_t al[4][4];
#pragma unroll
                for (int mt = 0; mt < 4; mt++)
                    LDSM4(al[mt][0], al[mt][1], al[mt][2], al[mt][3],
                          ab + STG_A + mt * (16 * PITCH_B) + off);
#pragma unroll
                for (int mt = 0; mt < 4; mt++)
#pragma unroll
                    for (int nt = 0; nt < 8; nt++)
                        MMA16816(acc[mt][nt], al[mt], bh[nt]);
            }
            {   // hi(A) x lo(B)
                uint32_t bl[8][2];
#pragma unroll
                for (int p = 0; p < 4; p++)
                    LDSM4(bl[2*p][0], bl[2*p][1], bl[2*p+1][0], bl[2*p+1][1],
                          bb + STG_B + p * (16 * PITCH_B) + off);
#pragma unroll
                for (int mt = 0; mt < 4; mt++)
#pragma unroll
                    for (int nt = 0; nt < 8; nt++)
                        MMA16816(acc[mt][nt], ah[mt], bl[nt]);
            }
        }
        __syncthreads();
        if (kc + 2 < 8) { load_stage((kc + 2) % 3, kc + 2); }
        CP_COMMIT();
    }

    // ---- epilogue ----
    const int r0 = row0 + wm * 64 + (lane >> 2);
    const int c0 = wn * 64 + (lane & 3) * 2;

    if (dosm) {
        // head-group softmax: groups are nt[0..3] and nt[4..7]
#pragma unroll
        for (int mt = 0; mt < 4; mt++)
#pragma unroll
            for (int g = 0; g < 2; g++)
#pragma unroll
                for (int h = 0; h < 2; h++) {
                    float mx = -1e30f;
#pragma unroll
                    for (int q = 0; q < 4; q++) {
                        const int nt = g * 4 + q;
                        mx = fmaxf(mx, fmaxf(acc[mt][nt][2*h], acc[mt][nt][2*h+1]));
                    }
                    mx = fmaxf(mx, __shfl_xor_sync(0xffffffffu, mx, 1));
                    mx = fmaxf(mx, __shfl_xor_sync(0xffffffffu, mx, 2));
                    float s = 0.f;
#pragma unroll
                    for (int q = 0; q < 4; q++) {
                        const int nt = g * 4 + q;
                        acc[mt][nt][2*h]   = __expf(acc[mt][nt][2*h]   - mx);
                        acc[mt][nt][2*h+1] = __expf(acc[mt][nt][2*h+1] - mx);
                        s += acc[mt][nt][2*h] + acc[mt][nt][2*h+1];
                    }
                    s += __shfl_xor_sync(0xffffffffu, s, 1);
                    s += __shfl_xor_sync(0xffffffffu, s, 2);
                    const float inv = 1.0f / s;
#pragma unroll
                    for (int q = 0; q < 4; q++) {
                        const int nt = g * 4 + q;
                        acc[mt][nt][2*h]   *= inv;
                        acc[mt][nt][2*h+1] *= inv;
                    }
                }
        // write Pq as bf16 hi/lo
#pragma unroll
        for (int mt = 0; mt < 4; mt++)
#pragma unroll
            for (int nt = 0; nt < 8; nt++) {
                const int r = r0 + mt * 16, c = c0 + nt * 8;
                uint32_t h0, l0, h1, l1;
                split2(acc[mt][nt][0], acc[mt][nt][1], h0, l0);
                split2(acc[mt][nt][2], acc[mt][nt][3], h1, l1);
                *(uint32_t*)(Ph + (size_t)r * 256 + c)       = h0;
                *(uint32_t*)(Pl + (size_t)r * 256 + c)       = l0;
                *(uint32_t*)(Ph + (size_t)(r + 8) * 256 + c) = h1;
                *(uint32_t*)(Pl + (size_t)(r + 8) * 256 + c) = l1;
            }
    } else {
#pragma unroll
        for (int mt = 0; mt < 4; mt++)
#pragma unroll
            for (int nt = 0; nt < 8; nt++) {
                const int r = r0 + mt * 16, c = c0 + nt * 8;
                *(float2*)&C[(size_t)r * 256 + c] =
                    make_float2(acc[mt][nt][0], acc[mt][nt][1]);
                *(float2*)&C[(size_t)(r + 8) * 256 + c] =
                    make_float2(acc[mt][nt][2], acc[mt][nt][3]);
            }
    }
}

// -------------------- k column softmax statistics (known-good) -------------
__global__ void __launch_bounds__(256) kstat_part(
    const float* __restrict__ Pk, float* __restrict__ pmax, float* __restrict__ psum)
{
    const int bf = blockIdx.x, ch = blockIdx.y, t = threadIdx.x;
    const float* p = Pk + ((size_t)bf * NSPA + ch * 256) * 256 + t;
    float m = -1e30f;
#pragma unroll 8
    for (int r = 0; r < 256; r++) m = fmaxf(m, p[(size_t)r * 256]);
    float s = 0.f;
#pragma unroll 8
    for (int r = 0; r < 256; r++) s += __expf(p[(size_t)r * 256] - m);
    const int o = (bf * 16 + ch) * 256 + t;
    pmax[o] = m;
    psum[o] = s;
}

__global__ void __launch_bounds__(256) kstat_merge(
    const float* __restrict__ pmax, const float* __restrict__ psum,
    float* __restrict__ cmax, float* __restrict__ cinv)
{
    const int bf = blockIdx.x, t = threadIdx.x;
    float m = -1e30f;
#pragma unroll
    for (int ch = 0; ch < 16; ch++) m = fmaxf(m, pmax[(bf * 16 + ch) * 256 + t]);
    float s = 0.f;
#pragma unroll
    for (int ch = 0; ch < 16; ch++) {
        const int o = (bf * 16 + ch) * 256 + t;
        s += psum[o] * __expf(pmax[o] - m);
    }
    cmax[bf * 256 + t] = m;
    cinv[bf * 256 + t] = 1.0f / s;
}

// -------------------- context (32x32) + W2 fold (known-good) ---------------
__global__ void __launch_bounds__(256) ctx_w2_kernel(
    const float* __restrict__ Pk, const float* __restrict__ Pv,
    const float* __restrict__ cmax, const float* __restrict__ cinv,
    const float* __restrict__ Wo, float* __restrict__ W2)
{
    __shared__ float sk[64 * 32];
    __shared__ float sv[64 * 32];
    __shared__ float sC[32 * 32];
    __shared__ float scmax[32];

    const int bf = blockIdx.x, h = blockIdx.y;
    const int t = threadIdx.x;
    const int d = t & 31, eg = t >> 5, e0 = eg * 4;

    if (t < 32) scmax[t] = cmax[bf * 256 + h * 32 + t];
    __syncthreads();

    float acc0 = 0.f, acc1 = 0.f, acc2 = 0.f, acc3 = 0.f;
    const float* pkb = Pk + (size_t)bf * NSPA * 256 + h * 32;
    const float* pvb = Pv + (size_t)bf * NSPA * 256 + h * 32;

    for (int n0 = 0; n0 < NSPA; n0 += 64) {
#pragma unroll
        for (int i = 0; i < 2; i++) {
            const int idx = t + i * 256;
            const int rr = idx >> 3, c4 = (idx & 7) * 4;
            const float4 kv = *(const float4*)(pkb + (size_t)(n0 + rr) * 256 + c4);
            const float4 vv = *(const float4*)(pvb + (size_t)(n0 + rr) * 256 + c4);
            float4 ke;
            ke.x = __expf(kv.x - scmax[c4 + 0]);
            ke.y = __expf(kv.y - scmax[c4 + 1]);
            ke.z = __expf(kv.z - scmax[c4 + 2]);
            ke.w = __expf(kv.w - scmax[c4 + 3]);
            *(float4*)&sk[rr * 32 + c4] = ke;
            *(float4*)&sv[rr * 32 + c4] = vv;
        }
        __syncthreads();
#pragma unroll 8
        for (int nn = 0; nn < 64; nn++) {
            const float kd = sk[nn * 32 + d];
            const float4 v4 = *(const float4*)&sv[nn * 32 + e0];
            acc0 += kd * v4.x;
            acc1 += kd * v4.y;
            acc2 += kd * v4.z;
            acc3 += kd * v4.w;
        }
        __syncthreads();
    }

    const float inv = cinv[bf * 256 + h * 32 + d];
    sC[d * 32 + e0 + 0] = acc0 * inv;
    sC[d * 32 + e0 + 1] = acc1 * inv;
    sC[d * 32 + e0 + 2] = acc2 * inv;
    sC[d * 32 + e0 + 3] = acc3 * inv;
    __syncthreads();

    float wo[32];
#pragma unroll
    for (int e = 0; e < 32; e++) wo[e] = Wo[(size_t)(h * 32 + e) * 256 + t];
    float* w2p = W2 + ((size_t)bf * 256 + h * 32) * 256 + t;
    for (int d2 = 0; d2 < 32; d2++) {
        float s = 0.f;
#pragma unroll
        for (int e = 0; e < 32; e++) s += sC[d2 * 32 + e] * wo[e];
        w2p[(size_t)d2 * 256] = s;
    }
}

// ------------------------------ launcher -----------------------------------
extern "C" void kernel_launch(void* const* d_in, const int* in_sizes, int n_in,
                              void* d_out, int out_size)
{
    (void)in_sizes; (void)n_in; (void)out_size;
    const float* x  = (const float*)d_in[0];
    const float* Wq = (const float*)d_in[1];
    const float* Wk = (const float*)d_in[2];
    const float* Wv = (const float*)d_in[3];
    const float* Wo = (const float*)d_in[4];
    float* out = (float*)d_out;

    float *Pk, *Pv, *pmax, *psum, *cmax, *cinv, *W2;
    __nv_bfloat16 *Xh, *Xl, *Pqh, *Pql, *Wth, *Wtl, *W2th, *W2tl;
    cudaGetSymbolAddress((void**)&Pk,   g_Pk);
    cudaGetSymbolAddress((void**)&Pv,   g_Pv);
    cudaGetSymbolAddress((void**)&Xh,   g_Xh);
    cudaGetSymbolAddress((void**)&Xl,   g_Xl);
    cudaGetSymbolAddress((void**)&Pqh,  g_Pqh);
    cudaGetSymbolAddress((void**)&Pql,  g_Pql);
    cudaGetSymbolAddress((void**)&pmax, g_pmax);
    cudaGetSymbolAddress((void**)&psum, g_psum);
    cudaGetSymbolAddress((void**)&cmax, g_cmax);
    cudaGetSymbolAddress((void**)&cinv, g_cinv);
    cudaGetSymbolAddress((void**)&W2,   g_W2);
    cudaGetSymbolAddress((void**)&Wth,  g_Wt_hi);
    cudaGetSymbolAddress((void**)&Wtl,  g_Wt_lo);
    cudaGetSymbolAddress((void**)&W2th, g_W2t_hi);
    cudaGetSymbolAddress((void**)&W2tl, g_W2t_lo);

    cudaFuncSetAttribute(mma_gemm, cudaFuncAttributeMaxDynamicSharedMemorySize,
                         SMEM_TOTAL);

    xsplit<<<MROWS * 256 / 1024, 256>>>(x, Xh, Xl);

    const dim3 tb(32, 8);
    tsplit<<<dim3(8, 8, 1), tb>>>(Wq, Wth,          Wtl);
    tsplit<<<dim3(8, 8, 1), tb>>>(Wk, Wth + 65536,  Wtl + 65536);
    tsplit<<<dim3(8, 8, 1), tb>>>(Wv, Wth + 131072, Wtl + 131072);

    // projections: Pq (softmax -> bf16 hi/lo), Pk, Pv (fp32)
    mma_gemm<<<dim3(3, MROWS / 128), 256, SMEM_TOTAL>>>(
        Xh, Xl, Wth, Wtl, nullptr, Pk, Pv, Pqh, Pql, 0, 1);

    kstat_part<<<dim3(BFU, 16), 256>>>(Pk, pmax, psum);
    kstat_merge<<<BFU, 256>>>(pmax, psum, cmax, cinv);
    ctx_w2_kernel<<<dim3(BFU, HEADS), 256>>>(Pk, Pv, cmax, cinv, Wo, W2);

    tsplit<<<dim3(8, 8, BFU), tb>>>(W2, W2th, W2tl);

    // out = Pq @ W2[bf]
    mma_gemm<<<dim3(1, MROWS / 128), 256, SMEM_TOTAL>>>(
        Pqh, Pql, W2th, W2tl, out, nullptr, nullptr, nullptr, nullptr, 1, 0);
}

// round 9
// speedup vs baseline: 1.7616x; 1.0845x over previous
#include <cuda_runtime.h>
#include <cuda_bf16.h>
#include <cstdint>
#include <math.h>

// ---------------------------------------------------------------------------
// SpatialLinearAttention — mma.sync bf16 hi/lo split GEMMs, cp.async 3-stage
// pipeline (single-sync mainloop), CTA tile 128x256 (warp tile 64x64).
// kstat pass-1 fused into the Pk GEMM epilogue.
//
//   0) xsplit    : X fp32 -> Xh/Xl bf16 (row-major)
//   1) tsplit x3 : Wq/Wk/Wv -> transposed [n][k] bf16 hi/lo
//   2) mma_gemm  : Pq/Pk/Pv = X @ W  (w = blockIdx.x; Pq: fused softmax ->
//                  bf16 hi/lo output; Pk: fp32 + fused column stats; Pv fp32)
//   3) kstat_merge : merge 32 per-CTA partials per (bf, col)
//   4) ctx_w2    : per (bf,head) 32x32 context + fold with Wo -> W2 (fp32)
//   5) tsplit    : W2 -> transposed bf16 hi/lo (batched 32)
//   6) mma_gemm  : out = Pq @ W2[bf]  (fp32 out)
// ---------------------------------------------------------------------------

#define BFU   32
#define NSPA  4096
#define HEADS 8
#define MROWS (BFU*NSPA)   // 131072

// ------------------------------- scratch ----------------------------------
__device__ __align__(128) float g_Pk[(size_t)MROWS * 256];
__device__ __align__(128) float g_Pv[(size_t)MROWS * 256];
__device__ __align__(128) __nv_bfloat16 g_Xh[(size_t)MROWS * 256];
__device__ __align__(128) __nv_bfloat16 g_Xl[(size_t)MROWS * 256];
__device__ __align__(128) __nv_bfloat16 g_Pqh[(size_t)MROWS * 256];
__device__ __align__(128) __nv_bfloat16 g_Pql[(size_t)MROWS * 256];
__device__ __align__(128) float g_pmax[1024 * 256];   // per 128-row CTA block
__device__ __align__(128) float g_psum[1024 * 256];
__device__ __align__(128) float g_cmax[BFU * 256];
__device__ __align__(128) float g_cinv[BFU * 256];
__device__ __align__(128) float g_W2[(size_t)BFU * 256 * 256];
__device__ __align__(128) __nv_bfloat16 g_Wt_hi[3 * 65536];
__device__ __align__(128) __nv_bfloat16 g_Wt_lo[3 * 65536];
__device__ __align__(128) __nv_bfloat16 g_W2t_hi[(size_t)BFU * 65536];
__device__ __align__(128) __nv_bfloat16 g_W2t_lo[(size_t)BFU * 65536];

// ----------------------------- helpers -------------------------------------
__device__ __forceinline__ uint32_t smem_u32(const void* p) {
    uint32_t a;
    asm("{ .reg .u64 t; cvta.to.shared.u64 t, %1; cvt.u32.u64 %0, t; }"
        : "=r"(a) : "l"(p));
    return a;
}

__device__ __forceinline__ void split2(float x, float y,
                                       unsigned int& h, unsigned int& l) {
    __nv_bfloat16 hx = __float2bfloat16(x), hy = __float2bfloat16(y);
    float rx = x - __bfloat162float(hx), ry = y - __bfloat162float(hy);
    h = (uint32_t)__bfloat16_as_ushort(hx) |
        ((uint32_t)__bfloat16_as_ushort(hy) << 16);
    l = (uint32_t)__bfloat16_as_ushort(__float2bfloat16(rx)) |
        ((uint32_t)__bfloat16_as_ushort(__float2bfloat16(ry)) << 16);
}

#define LDSM4(R0, R1, R2, R3, ADDR) \
    asm volatile("ldmatrix.sync.aligned.m8n8.x4.shared.b16 {%0,%1,%2,%3}, [%4];" \
        : "=r"(R0), "=r"(R1), "=r"(R2), "=r"(R3) : "r"(ADDR))

#define MMA16816(D, Af, Bf) \
    asm volatile("mma.sync.aligned.m16n8k16.row.col.f32.bf16.bf16.f32 " \
        "{%0,%1,%2,%3}, {%4,%5,%6,%7}, {%8,%9}, {%0,%1,%2,%3};" \
        : "+f"((D)[0]), "+f"((D)[1]), "+f"((D)[2]), "+f"((D)[3]) \
        : "r"((Af)[0]), "r"((Af)[1]), "r"((Af)[2]), "r"((Af)[3]), \
          "r"((Bf)[0]), "r"((Bf)[1]))

#define CPA16(DST, SRC) \
    asm volatile("cp.async.cg.shared.global [%0], [%1], 16;" \
        :: "r"(DST), "l"(SRC) : "memory")
#define CP_COMMIT() asm volatile("cp.async.commit_group;" ::: "memory")
#define CP_WAIT1()  asm volatile("cp.async.wait_group 1;" ::: "memory")
#define CP_WAIT0()  asm volatile("cp.async.wait_group 0;" ::: "memory")

// -------------------------- X fp32 -> bf16 hi/lo ---------------------------
__global__ void __launch_bounds__(256) xsplit(
    const float* __restrict__ src,
    __nv_bfloat16* __restrict__ dh, __nv_bfloat16* __restrict__ dl)
{
    const size_t i = ((size_t)blockIdx.x * 256 + threadIdx.x) * 4;
    const float4 v = *(const float4*)(src + i);
    uint2 h, l;
    split2(v.x, v.y, h.x, l.x);
    split2(v.z, v.w, h.y, l.y);
    *(uint2*)(dh + i) = h;
    *(uint2*)(dl + i) = l;
}

// --------------------- weight transpose + bf16 split -----------------------
__global__ void __launch_bounds__(256) tsplit(
    const float* __restrict__ src,
    __nv_bfloat16* __restrict__ dhi, __nv_bfloat16* __restrict__ dlo)
{
    __shared__ float t[32][33];
    const size_t base = (size_t)blockIdx.z * 65536;
    const int tx = threadIdx.x, ty = threadIdx.y;
    const int xs = blockIdx.x * 32 + tx;
    const int ys = blockIdx.y * 32;
#pragma unroll
    for (int j = 0; j < 32; j += 8)
        t[ty + j][tx] = src[base + (size_t)(ys + ty + j) * 256 + xs];
    __syncthreads();
    const int xo = blockIdx.y * 32 + tx;
    const int yo = blockIdx.x * 32;
#pragma unroll
    for (int j = 0; j < 32; j += 8) {
        const float v = t[tx][ty + j];
        const __nv_bfloat16 h = __float2bfloat16(v);
        const float r = v - __bfloat162float(h);
        dhi[base + (size_t)(yo + ty + j) * 256 + xo] = h;
        dlo[base + (size_t)(yo + ty + j) * 256 + xo] = __float2bfloat16(r);
    }
}

// ----------------------------- mma.sync GEMM -------------------------------
// C[128-row block, 256] = A[.,256] @ B (bf16 hi/lo, [n][k]).
// grid (W, 1024). 3-term split (AhBh + AlBh + AhBl) in fp32 accumulators.
// w==0 && qmode: fused head-group softmax, bf16 hi/lo output.
// w==1 && qmode: fused per-column (max, sumexp) partials -> g_pmax/g_psum.
#define PITCH_B 80               // bytes per smem row (40 bf16), conflict-free
#define STG_A   10240            // A-hi bytes per stage (128 rows x 80)
#define STG_B   20480            // B-hi bytes per stage (256 rows x 80)
#define STAGE_BYTES (2*STG_A + 2*STG_B)   // 61440
#define NSTAGE  3
#define SMEM_TOTAL (NSTAGE * STAGE_BYTES) // 184320

__global__ void __launch_bounds__(256, 1) mma_gemm(
    const __nv_bfloat16* __restrict__ Ah, const __nv_bfloat16* __restrict__ Al,
    const __nv_bfloat16* __restrict__ Bhi, const __nv_bfloat16* __restrict__ Blo,
    float* __restrict__ C0, float* __restrict__ C1, float* __restrict__ C2,
    __nv_bfloat16* __restrict__ Ph, __nv_bfloat16* __restrict__ Pl,
    float* __restrict__ pmax, float* __restrict__ psum,
    int batchB, int qmode)
{
    extern __shared__ __align__(16) unsigned char sm[];
    const uint32_t sb = smem_u32(sm);
    const int tid = threadIdx.x, lane = tid & 31, wid = tid >> 5;
    const int wm = wid & 1, wn = wid >> 1;      // warp grid 2(m) x 4(n), 64x64
    const int w = blockIdx.x, mb = blockIdx.y;
    const int row0 = mb * 128;

    size_t boff = (size_t)w * 65536;
    if (batchB) boff += (size_t)(mb >> 5) * 65536;
    const __nv_bfloat16* BH = Bhi + boff;
    const __nv_bfloat16* BL = Blo + boff;
    float* C = (w == 0) ? C0 : ((w == 1) ? C1 : C2);
    const int dosm = qmode && (w == 0);
    const int dost = qmode && (w == 1);

    const __nv_bfloat16* AHg = Ah + (size_t)row0 * 256;
    const __nv_bfloat16* ALg = Al + (size_t)row0 * 256;

    // per-thread cp.async assignments
    const int a_r0 = tid >> 2, a_j = (tid & 3) * 8;
    const int b_r0 = tid >> 2, b_j = (tid & 3) * 8;

    // ldmatrix lane addressing (byte offsets within a stage)
    const uint32_t a_off =
        (uint32_t)((wm * 64 + (lane & 15)) * PITCH_B + (lane >> 4) * 16);
    const int bn_l = (lane & 7) + ((lane >> 4) & 1) * 8;
    const int bk_l = ((lane >> 3) & 1) * 16;
    const uint32_t b_off = 2 * STG_A +
        (uint32_t)((wn * 64 + bn_l) * PITCH_B + bk_l);

    float acc[4][8][4];
#pragma unroll
    for (int i = 0; i < 4; i++)
#pragma unroll
        for (int j = 0; j < 8; j++)
#pragma unroll
            for (int r = 0; r < 4; r++) acc[i][j][r] = 0.f;

    auto load_stage = [&](int stage, int kc) {
        const uint32_t sd = sb + stage * STAGE_BYTES;
        const int k0 = kc * 32;
#pragma unroll
        for (int i = 0; i < 2; i++) {               // A: 128 rows
            const int r = a_r0 + i * 64;
            const uint32_t d = sd + (uint32_t)(r * PITCH_B) + (a_j * 2);
            const size_t s = (size_t)r * 256 + k0 + a_j;
            CPA16(d,         AHg + s);
            CPA16(d + STG_A, ALg + s);
        }
#pragma unroll
        for (int i = 0; i < 4; i++) {               // B: 256 rows
            const int r = b_r0 + i * 64;
            const uint32_t d = sd + 2 * STG_A + (uint32_t)(r * PITCH_B) + (b_j * 2);
            const size_t s = (size_t)r * 256 + k0 + b_j;
            CPA16(d,         BH + s);
            CPA16(d + STG_B, BL + s);
        }
    };

    load_stage(0, 0); CP_COMMIT();
    load_stage(1, 1); CP_COMMIT();

    for (int kc = 0; kc < 8; kc++) {
        // stage kc must have arrived. Iterations 0..5 hold 2 groups in flight
        // (kc, kc+1); 6 holds 1; 7 holds 0 — match the wait accordingly.
        if (kc < 6) CP_WAIT1(); else CP_WAIT0();
        __syncthreads();       // also fences slot (kc+2)%3 == (kc-1)%3 reuse

        // issue next stage's loads first: max overlap with the MMA block
        if (kc < 6) { load_stage((kc + 2) % 3, kc + 2); CP_COMMIT(); }

        const uint32_t st = sb + (kc % 3) * STAGE_BYTES;
        const uint32_t ab = st + a_off, bb = st + b_off;

#pragma unroll
        for (int ks = 0; ks < 2; ks++) {
            const uint32_t off = ks * 32;
            uint32_t ah[4][4], al[4][4], bh[8][2], bl[8][2];
#pragma unroll
            for (int mt = 0; mt < 4; mt++)
                LDSM4(ah[mt][0], ah[mt][1], ah[mt][2], ah[mt][3],
                      ab + mt * (16 * PITCH_B) + off);
#pragma unroll
            for (int p = 0; p < 4; p++)
                LDSM4(bh[2*p][0], bh[2*p][1], bh[2*p+1][0], bh[2*p+1][1],
                      bb + p * (16 * PITCH_B) + off);
#pragma unroll
            for (int mt = 0; mt < 4; mt++)
                LDSM4(al[mt][0], al[mt][1], al[mt][2], al[mt][3],
                      ab + STG_A + mt * (16 * PITCH_B) + off);
#pragma unroll
            for (int p = 0; p < 4; p++)
                LDSM4(bl[2*p][0], bl[2*p][1], bl[2*p+1][0], bl[2*p+1][1],
                      bb + STG_B + p * (16 * PITCH_B) + off);
#pragma unroll
            for (int mt = 0; mt < 4; mt++)
#pragma unroll
                for (int nt = 0; nt < 8; nt++)
                    MMA16816(acc[mt][nt], ah[mt], bh[nt]);
#pragma unroll
            for (int mt = 0; mt < 4; mt++)
#pragma unroll
                for (int nt = 0; nt < 8; nt++)
                    MMA16816(acc[mt][nt], al[mt], bh[nt]);
#pragma unroll
            for (int mt = 0; mt < 4; mt++)
#pragma unroll
                for (int nt = 0; nt < 8; nt++)
                    MMA16816(acc[mt][nt], ah[mt], bl[nt]);
        }
        // no trailing sync: next iteration's sync covers slot reuse
    }

    // ---- epilogue ----
    const int r0 = row0 + wm * 64 + (lane >> 2);
    const int c0 = wn * 64 + (lane & 3) * 2;

    if (dosm) {
        // head-group softmax: groups are nt[0..3] and nt[4..7]
#pragma unroll
        for (int mt = 0; mt < 4; mt++)
#pragma unroll
            for (int g = 0; g < 2; g++)
#pragma unroll
                for (int h = 0; h < 2; h++) {
                    float mx = -1e30f;
#pragma unroll
                    for (int q = 0; q < 4; q++) {
                        const int nt = g * 4 + q;
                        mx = fmaxf(mx, fmaxf(acc[mt][nt][2*h], acc[mt][nt][2*h+1]));
                    }
                    mx = fmaxf(mx, __shfl_xor_sync(0xffffffffu, mx, 1));
                    mx = fmaxf(mx, __shfl_xor_sync(0xffffffffu, mx, 2));
                    float s = 0.f;
#pragma unroll
                    for (int q = 0; q < 4; q++) {
                        const int nt = g * 4 + q;
                        acc[mt][nt][2*h]   = __expf(acc[mt][nt][2*h]   - mx);
                        acc[mt][nt][2*h+1] = __expf(acc[mt][nt][2*h+1] - mx);
                        s += acc[mt][nt][2*h] + acc[mt][nt][2*h+1];
                    }
                    s += __shfl_xor_sync(0xffffffffu, s, 1);
                    s += __shfl_xor_sync(0xffffffffu, s, 2);
                    const float inv = 1.0f / s;
#pragma unroll
                    for (int q = 0; q < 4; q++) {
                        const int nt = g * 4 + q;
                        acc[mt][nt][2*h]   *= inv;
                        acc[mt][nt][2*h+1] *= inv;
                    }
                }
        // write Pq as bf16 hi/lo
#pragma unroll
        for (int mt = 0; mt < 4; mt++)
#pragma unroll
            for (int nt = 0; nt < 8; nt++) {
                const int r = r0 + mt * 16, c = c0 + nt * 8;
                uint32_t h0, l0, h1, l1;
                split2(acc[mt][nt][0], acc[mt][nt][1], h0, l0);
                split2(acc[mt][nt][2], acc[mt][nt][3], h1, l1);
                *(uint32_t*)(Ph + (size_t)r * 256 + c)       = h0;
                *(uint32_t*)(Pl + (size_t)r * 256 + c)       = l0;
                *(uint32_t*)(Ph + (size_t)(r + 8) * 256 + c) = h1;
                *(uint32_t*)(Pl + (size_t)(r + 8) * 256 + c) = l1;
            }
        return;
    }

    // fp32 store (Pk / Pv / out)
#pragma unroll
    for (int mt = 0; mt < 4; mt++)
#pragma unroll
        for (int nt = 0; nt < 8; nt++) {
            const int r = r0 + mt * 16, c = c0 + nt * 8;
            *(float2*)&C[(size_t)r * 256 + c] =
                make_float2(acc[mt][nt][0], acc[mt][nt][1]);
            *(float2*)&C[(size_t)(r + 8) * 256 + c] =
                make_float2(acc[mt][nt][2], acc[mt][nt][3]);
        }

    if (dost) {
        // fused kstat pass-1: per-column max & sumexp over this 128-row block.
        // thread's 16 columns: c = c0 + nt*8 + j; 8 values each (4 mt x 2 halves)
        float cm[16], cs[16];
#pragma unroll
        for (int nt = 0; nt < 8; nt++)
#pragma unroll
            for (int j = 0; j < 2; j++) {
                const int idx = nt * 2 + j;
                float m = -1e30f;
#pragma unroll
                for (int mt = 0; mt < 4; mt++)
                    m = fmaxf(m, fmaxf(acc[mt][nt][j], acc[mt][nt][j + 2]));
                m = fmaxf(m, __shfl_xor_sync(0xffffffffu, m, 4));
                m = fmaxf(m, __shfl_xor_sync(0xffffffffu, m, 8));
                m = fmaxf(m, __shfl_xor_sync(0xffffffffu, m, 16));
                float s = 0.f;
#pragma unroll
                for (int mt = 0; mt < 4; mt++)
                    s += __expf(acc[mt][nt][j] - m) + __expf(acc[mt][nt][j + 2] - m);
                s += __shfl_xor_sync(0xffffffffu, s, 4);
                s += __shfl_xor_sync(0xffffffffu, s, 8);
                s += __shfl_xor_sync(0xffffffffu, s, 16);
                cm[idx] = m;
                cs[idx] = s;
            }
        __syncthreads();                 // mainloop smem no longer needed
        float* fst = (float*)sm;         // [wm][wn][64 cols][2]
        if ((lane >> 2) == 0) {
#pragma unroll
            for (int idx = 0; idx < 16; idx++) {
                const int cl = (lane & 3) * 2 + (idx >> 1) * 8 + (idx & 1);
                const int o = (((wm * 4 + wn) * 64) + cl) * 2;
                fst[o]     = cm[idx];
                fst[o + 1] = cs[idx];
            }
        }
        __syncthreads();
        const int wn2 = tid >> 6, cl = tid & 63;
        const float m0 = fst[((0 * 4 + wn2) * 64 + cl) * 2];
        const float s0 = fst[((0 * 4 + wn2) * 64 + cl) * 2 + 1];
        const float m1 = fst[((1 * 4 + wn2) * 64 + cl) * 2];
        const float s1 = fst[((1 * 4 + wn2) * 64 + cl) * 2 + 1];
        const float M = fmaxf(m0, m1);
        const float S = s0 * __expf(m0 - M) + s1 * __expf(m1 - M);
        pmax[(size_t)mb * 256 + wn2 * 64 + cl] = M;
        psum[(size_t)mb * 256 + wn2 * 64 + cl] = S;
    }
}

// -------------------- k column stats merge (32 chunks/bf) ------------------
__global__ void __launch_bounds__(256) kstat_merge(
    const float* __restrict__ pmax, const float* __restrict__ psum,
    float* __restrict__ cmax, float* __restrict__ cinv)
{
    const int bf = blockIdx.x, t = threadIdx.x;
    float m = -1e30f;
#pragma unroll
    for (int ch = 0; ch < 32; ch++)
        m = fmaxf(m, pmax[(size_t)(bf * 32 + ch) * 256 + t]);
    float s = 0.f;
#pragma unroll
    for (int ch = 0; ch < 32; ch++) {
        const size_t o = (size_t)(bf * 32 + ch) * 256 + t;
        s += psum[o] * __expf(pmax[o] - m);
    }
    cmax[bf * 256 + t] = m;
    cinv[bf * 256 + t] = 1.0f / s;
}

// -------------------- context (32x32) + W2 fold (known-good) ---------------
__global__ void __launch_bounds__(256) ctx_w2_kernel(
    const float* __restrict__ Pk, const float* __restrict__ Pv,
    const float* __restrict__ cmax, const float* __restrict__ cinv,
    const float* __restrict__ Wo, float* __restrict__ W2)
{
    __shared__ float sk[64 * 32];
    __shared__ float sv[64 * 32];
    __shared__ float sC[32 * 32];
    __shared__ float scmax[32];

    const int bf = blockIdx.x, h = blockIdx.y;
    const int t = threadIdx.x;
    const int d = t & 31, eg = t >> 5, e0 = eg * 4;

    if (t < 32) scmax[t] = cmax[bf * 256 + h * 32 + t];
    __syncthreads();

    float acc0 = 0.f, acc1 = 0.f, acc2 = 0.f, acc3 = 0.f;
    const float* pkb = Pk + (size_t)bf * NSPA * 256 + h * 32;
    const float* pvb = Pv + (size_t)bf * NSPA * 256 + h * 32;

    for (int n0 = 0; n0 < NSPA; n0 += 64) {
#pragma unroll
        for (int i = 0; i < 2; i++) {
            const int idx = t + i * 256;
            const int rr = idx >> 3, c4 = (idx & 7) * 4;
            const float4 kv = *(const float4*)(pkb + (size_t)(n0 + rr) * 256 + c4);
            const float4 vv = *(const float4*)(pvb + (size_t)(n0 + rr) * 256 + c4);
            float4 ke;
            ke.x = __expf(kv.x - scmax[c4 + 0]);
            ke.y = __expf(kv.y - scmax[c4 + 1]);
            ke.z = __expf(kv.z - scmax[c4 + 2]);
            ke.w = __expf(kv.w - scmax[c4 + 3]);
            *(float4*)&sk[rr * 32 + c4] = ke;
            *(float4*)&sv[rr * 32 + c4] = vv;
        }
        __syncthreads();
#pragma unroll 8
        for (int nn = 0; nn < 64; nn++) {
            const float kd = sk[nn * 32 + d];
            const float4 v4 = *(const float4*)&sv[nn * 32 + e0];
            acc0 += kd * v4.x;
            acc1 += kd * v4.y;
            acc2 += kd * v4.z;
            acc3 += kd * v4.w;
        }
        __syncthreads();
    }

    const float inv = cinv[bf * 256 + h * 32 + d];
    sC[d * 32 + e0 + 0] = acc0 * inv;
    sC[d * 32 + e0 + 1] = acc1 * inv;
    sC[d * 32 + e0 + 2] = acc2 * inv;
    sC[d * 32 + e0 + 3] = acc3 * inv;
    __syncthreads();

    float wo[32];
#pragma unroll
    for (int e = 0; e < 32; e++) wo[e] = Wo[(size_t)(h * 32 + e) * 256 + t];
    float* w2p = W2 + ((size_t)bf * 256 + h * 32) * 256 + t;
    for (int d2 = 0; d2 < 32; d2++) {
        float s = 0.f;
#pragma unroll
        for (int e = 0; e < 32; e++) s += sC[d2 * 32 + e] * wo[e];
        w2p[(size_t)d2 * 256] = s;
    }
}

// ------------------------------ launcher -----------------------------------
extern "C" void kernel_launch(void* const* d_in, const int* in_sizes, int n_in,
                              void* d_out, int out_size)
{
    (void)in_sizes; (void)n_in; (void)out_size;
    const float* x  = (const float*)d_in[0];
    const float* Wq = (const float*)d_in[1];
    const float* Wk = (const float*)d_in[2];
    const float* Wv = (const float*)d_in[3];
    const float* Wo = (const float*)d_in[4];
    float* out = (float*)d_out;

    float *Pk, *Pv, *pmax, *psum, *cmax, *cinv, *W2;
    __nv_bfloat16 *Xh, *Xl, *Pqh, *Pql, *Wth, *Wtl, *W2th, *W2tl;
    cudaGetSymbolAddress((void**)&Pk,   g_Pk);
    cudaGetSymbolAddress((void**)&Pv,   g_Pv);
    cudaGetSymbolAddress((void**)&Xh,   g_Xh);
    cudaGetSymbolAddress((void**)&Xl,   g_Xl);
    cudaGetSymbolAddress((void**)&Pqh,  g_Pqh);
    cudaGetSymbolAddress((void**)&Pql,  g_Pql);
    cudaGetSymbolAddress((void**)&pmax, g_pmax);
    cudaGetSymbolAddress((void**)&psum, g_psum);
    cudaGetSymbolAddress((void**)&cmax, g_cmax);
    cudaGetSymbolAddress((void**)&cinv, g_cinv);
    cudaGetSymbolAddress((void**)&W2,   g_W2);
    cudaGetSymbolAddress((void**)&Wth,  g_Wt_hi);
    cudaGetSymbolAddress((void**)&Wtl,  g_Wt_lo);
    cudaGetSymbolAddress((void**)&W2th, g_W2t_hi);
    cudaGetSymbolAddress((void**)&W2tl, g_W2t_lo);

    cudaFuncSetAttribute(mma_gemm, cudaFuncAttributeMaxDynamicSharedMemorySize,
                         SMEM_TOTAL);

    xsplit<<<MROWS * 256 / 1024, 256>>>(x, Xh, Xl);

    const dim3 tb(32, 8);
    tsplit<<<dim3(8, 8, 1), tb>>>(Wq, Wth,          Wtl);
    tsplit<<<dim3(8, 8, 1), tb>>>(Wk, Wth + 65536,  Wtl + 65536);
    tsplit<<<dim3(8, 8, 1), tb>>>(Wv, Wth + 131072, Wtl + 131072);

    // projections: Pq (softmax -> bf16 hi/lo), Pk (fp32 + stats), Pv (fp32)
    mma_gemm<<<dim3(3, MROWS / 128), 256, SMEM_TOTAL>>>(
        Xh, Xl, Wth, Wtl, nullptr, Pk, Pv, Pqh, Pql, pmax, psum, 0, 1);

    kstat_merge<<<BFU, 256>>>(pmax, psum, cmax, cinv);
    ctx_w2_kernel<<<dim3(BFU, HEADS), 256>>>(Pk, Pv, cmax, cinv, Wo, W2);

    tsplit<<<dim3(8, 8, BFU), tb>>>(W2, W2th, W2tl);

    // out = Pq @ W2[bf]
    mma_gemm<<<dim3(1, MROWS / 128), 256, SMEM_TOTAL>>>(
        Pqh, Pql, W2th, W2tl, out, nullptr, nullptr, nullptr, nullptr,
        nullptr, nullptr, 1, 0);
}

// round 10
// speedup vs baseline: 1.8902x; 1.0730x over previous
#include <cuda_runtime.h>
#include <cuda_bf16.h>
#include <cstdint>
#include <math.h>

// ---------------------------------------------------------------------------
// SpatialLinearAttention — mma.sync bf16 hi/lo split GEMMs.
// R9: CTA tile 128x128, warp tile 64x32, 2-stage cp.async pipeline, 80KB smem
// -> 2 CTAs/SM (hide prologue/sync/epilogue bubbles across CTAs).
//
//   0) xsplit    : X fp32 -> Xh/Xl bf16 (row-major)
//   1) tsplit x3 : Wq/Wk/Wv -> transposed [n][k] bf16 hi/lo
//   2) mma_gemm  : Pq/Pk/Pv = X @ W  (w = blockIdx.x; Pq: fused softmax ->
//                  bf16 hi/lo output; Pk: fp32 + fused column stats; Pv fp32)
//   3) kstat_merge : merge 32 per-CTA partials per (bf, col)
//   4) ctx_w2    : per (bf,head) 32x32 context + fold with Wo -> W2 (fp32)
//   5) tsplit    : W2 -> transposed bf16 hi/lo (batched 32)
//   6) mma_gemm  : out = Pq @ W2[bf]  (fp32 out)
// ---------------------------------------------------------------------------

#define BFU   32
#define NSPA  4096
#define HEADS 8
#define MROWS (BFU*NSPA)   // 131072

// ------------------------------- scratch ----------------------------------
__device__ __align__(128) float g_Pk[(size_t)MROWS * 256];
__device__ __align__(128) float g_Pv[(size_t)MROWS * 256];
__device__ __align__(128) __nv_bfloat16 g_Xh[(size_t)MROWS * 256];
__device__ __align__(128) __nv_bfloat16 g_Xl[(size_t)MROWS * 256];
__device__ __align__(128) __nv_bfloat16 g_Pqh[(size_t)MROWS * 256];
__device__ __align__(128) __nv_bfloat16 g_Pql[(size_t)MROWS * 256];
__device__ __align__(128) float g_pmax[1024 * 256];   // per 128-row block
__device__ __align__(128) float g_psum[1024 * 256];
__device__ __align__(128) float g_cmax[BFU * 256];
__device__ __align__(128) float g_cinv[BFU * 256];
__device__ __align__(128) float g_W2[(size_t)BFU * 256 * 256];
__device__ __align__(128) __nv_bfloat16 g_Wt_hi[3 * 65536];
__device__ __align__(128) __nv_bfloat16 g_Wt_lo[3 * 65536];
__device__ __align__(128) __nv_bfloat16 g_W2t_hi[(size_t)BFU * 65536];
__device__ __align__(128) __nv_bfloat16 g_W2t_lo[(size_t)BFU * 65536];

// ----------------------------- helpers -------------------------------------
__device__ __forceinline__ uint32_t smem_u32(const void* p) {
    uint32_t a;
    asm("{ .reg .u64 t; cvta.to.shared.u64 t, %1; cvt.u32.u64 %0, t; }"
        : "=r"(a) : "l"(p));
    return a;
}

__device__ __forceinline__ void split2(float x, float y,
                                       unsigned int& h, unsigned int& l) {
    __nv_bfloat16 hx = __float2bfloat16(x), hy = __float2bfloat16(y);
    float rx = x - __bfloat162float(hx), ry = y - __bfloat162float(hy);
    h = (uint32_t)__bfloat16_as_ushort(hx) |
        ((uint32_t)__bfloat16_as_ushort(hy) << 16);
    l = (uint32_t)__bfloat16_as_ushort(__float2bfloat16(rx)) |
        ((uint32_t)__bfloat16_as_ushort(__float2bfloat16(ry)) << 16);
}

#define LDSM4(R0, R1, R2, R3, ADDR) \
    asm volatile("ldmatrix.sync.aligned.m8n8.x4.shared.b16 {%0,%1,%2,%3}, [%4];" \
        : "=r"(R0), "=r"(R1), "=r"(R2), "=r"(R3) : "r"(ADDR))

#define MMA16816(D, Af, Bf) \
    asm volatile("mma.sync.aligned.m16n8k16.row.col.f32.bf16.bf16.f32 " \
        "{%0,%1,%2,%3}, {%4,%5,%6,%7}, {%8,%9}, {%0,%1,%2,%3};" \
        : "+f"((D)[0]), "+f"((D)[1]), "+f"((D)[2]), "+f"((D)[3]) \
        : "r"((Af)[0]), "r"((Af)[1]), "r"((Af)[2]), "r"((Af)[3]), \
          "r"((Bf)[0]), "r"((Bf)[1]))

#define CPA16(DST, SRC) \
    asm volatile("cp.async.cg.shared.global [%0], [%1], 16;" \
        :: "r"(DST), "l"(SRC) : "memory")
#define CP_COMMIT() asm volatile("cp.async.commit_group;" ::: "memory")
#define CP_WAIT0()  asm volatile("cp.async.wait_group 0;" ::: "memory")

// -------------------------- X fp32 -> bf16 hi/lo ---------------------------
__global__ void __launch_bounds__(256) xsplit(
    const float* __restrict__ src,
    __nv_bfloat16* __restrict__ dh, __nv_bfloat16* __restrict__ dl)
{
    const size_t i = ((size_t)blockIdx.x * 256 + threadIdx.x) * 4;
    const float4 v = *(const float4*)(src + i);
    uint2 h, l;
    split2(v.x, v.y, h.x, l.x);
    split2(v.z, v.w, h.y, l.y);
    *(uint2*)(dh + i) = h;
    *(uint2*)(dl + i) = l;
}

// --------------------- weight transpose + bf16 split -----------------------
__global__ void __launch_bounds__(256) tsplit(
    const float* __restrict__ src,
    __nv_bfloat16* __restrict__ dhi, __nv_bfloat16* __restrict__ dlo)
{
    __shared__ float t[32][33];
    const size_t base = (size_t)blockIdx.z * 65536;
    const int tx = threadIdx.x, ty = threadIdx.y;
    const int xs = blockIdx.x * 32 + tx;
    const int ys = blockIdx.y * 32;
#pragma unroll
    for (int j = 0; j < 32; j += 8)
        t[ty + j][tx] = src[base + (size_t)(ys + ty + j) * 256 + xs];
    __syncthreads();
    const int xo = blockIdx.y * 32 + tx;
    const int yo = blockIdx.x * 32;
#pragma unroll
    for (int j = 0; j < 32; j += 8) {
        const float v = t[tx][ty + j];
        const __nv_bfloat16 h = __float2bfloat16(v);
        const float r = v - __bfloat162float(h);
        dhi[base + (size_t)(yo + ty + j) * 256 + xo] = h;
        dlo[base + (size_t)(yo + ty + j) * 256 + xo] = __float2bfloat16(r);
    }
}

// ----------------------------- mma.sync GEMM -------------------------------
// C[128-row, 128-col block] = A[.,256] @ B (bf16 hi/lo, [n][k]).
// grid (W, 2048): blockIdx.y = mb*2 + cb. 3-term split in fp32 accumulators.
// w==0 && qmode: fused head-group softmax, bf16 hi/lo output.
// w==1 && qmode: fused per-column (max, sumexp) partials -> pmax/psum.
#define PITCH_B 80               // bytes per smem row (40 bf16), conflict-free
#define STG     10240            // one matrix tile per stage (128 rows x 80)
#define STAGE_BYTES (4*STG)      // A-hi, A-lo, B-hi, B-lo = 40960
#define NSTAGE  2
#define SMEM_TOTAL (NSTAGE * STAGE_BYTES) // 81920 -> 2 CTAs/SM

__global__ void __launch_bounds__(256, 2) mma_gemm(
    const __nv_bfloat16* __restrict__ Ah, const __nv_bfloat16* __restrict__ Al,
    const __nv_bfloat16* __restrict__ Bhi, const __nv_bfloat16* __restrict__ Blo,
    float* __restrict__ C0, float* __restrict__ C1, float* __restrict__ C2,
    __nv_bfloat16* __restrict__ Ph, __nv_bfloat16* __restrict__ Pl,
    float* __restrict__ pmax, float* __restrict__ psum,
    int batchB, int qmode)
{
    extern __shared__ __align__(16) unsigned char sm[];
    const uint32_t sb = smem_u32(sm);
    const int tid = threadIdx.x, lane = tid & 31, wid = tid >> 5;
    const int wm = wid & 1, wn = wid >> 1;      // warp grid 2(m) x 4(n), 64x32
    const int w = blockIdx.x;
    const int mb = blockIdx.y >> 1, cb = blockIdx.y & 1;
    const int row0 = mb * 128, col0 = cb * 128;

    size_t boff = (size_t)w * 65536;
    if (batchB) boff += (size_t)(mb >> 5) * 65536;
    const __nv_bfloat16* BHt = Bhi + boff + (size_t)col0 * 256;
    const __nv_bfloat16* BLt = Blo + boff + (size_t)col0 * 256;
    float* C = (w == 0) ? C0 : ((w == 1) ? C1 : C2);
    const int dosm = qmode && (w == 0);
    const int dost = qmode && (w == 1);

    const __nv_bfloat16* AHg = Ah + (size_t)row0 * 256;
    const __nv_bfloat16* ALg = Al + (size_t)row0 * 256;

    // cp.async: 128 rows x 64B per matrix; thread -> (row, 16B chunk)
    const int ld_r = tid >> 2, ld_j = (tid & 3) * 8;   // +64 rows second pass

    // ldmatrix lane addressing (byte offsets within a stage)
    const uint32_t a_off =
        (uint32_t)((wm * 64 + (lane & 15)) * PITCH_B + (lane >> 4) * 16);
    const int bn_l = (lane & 7) + ((lane >> 4) & 1) * 8;
    const int bk_l = ((lane >> 3) & 1) * 16;
    const uint32_t b_off = 2 * STG +
        (uint32_t)((wn * 32 + bn_l) * PITCH_B + bk_l);

    float acc[4][4][4];
#pragma unroll
    for (int i = 0; i < 4; i++)
#pragma unroll
        for (int j = 0; j < 4; j++)
#pragma unroll
            for (int r = 0; r < 4; r++) acc[i][j][r] = 0.f;

    auto load_stage = [&](int stage, int kc) {
        const uint32_t sd = sb + stage * STAGE_BYTES;
        const int k0 = kc * 32;
#pragma unroll
        for (int i = 0; i < 2; i++) {
            const int r = ld_r + i * 64;
            const uint32_t d = sd + (uint32_t)(r * PITCH_B) + (ld_j * 2);
            const size_t s = (size_t)r * 256 + k0 + ld_j;
            CPA16(d,           AHg + s);
            CPA16(d + STG,     ALg + s);
            CPA16(d + 2 * STG, BHt + s);
            CPA16(d + 3 * STG, BLt + s);
        }
    };

    load_stage(0, 0); CP_COMMIT();

    for (int kc = 0; kc < 8; kc++) {
        CP_WAIT0();            // stage kc has arrived (only group pending)
        __syncthreads();       // visibility + slot (kc+1)&1 free (kc-1 done)
        if (kc < 7) { load_stage((kc + 1) & 1, kc + 1); CP_COMMIT(); }

        const uint32_t st = sb + (kc & 1) * STAGE_BYTES;
        const uint32_t ab = st + a_off, bb = st + b_off;

#pragma unroll
        for (int ks = 0; ks < 2; ks++) {
            const uint32_t off = ks * 32;
            uint32_t ah[4][4], bh[4][2];
#pragma unroll
            for (int mt = 0; mt < 4; mt++)
                LDSM4(ah[mt][0], ah[mt][1], ah[mt][2], ah[mt][3],
                      ab + mt * (16 * PITCH_B) + off);
            LDSM4(bh[0][0], bh[0][1], bh[1][0], bh[1][1], bb + off);
            LDSM4(bh[2][0], bh[2][1], bh[3][0], bh[3][1],
                  bb + 16 * PITCH_B + off);
#pragma unroll
            for (int mt = 0; mt < 4; mt++)
#pragma unroll
                for (int nt = 0; nt < 4; nt++)
                    MMA16816(acc[mt][nt], ah[mt], bh[nt]);
            {   // lo(A) x hi(B)
                uint32_t al[4][4];
#pragma unroll
                for (int mt = 0; mt < 4; mt++)
                    LDSM4(al[mt][0], al[mt][1], al[mt][2], al[mt][3],
                          ab + STG + mt * (16 * PITCH_B) + off);
#pragma unroll
                for (int mt = 0; mt < 4; mt++)
#pragma unroll
                    for (int nt = 0; nt < 4; nt++)
                        MMA16816(acc[mt][nt], al[mt], bh[nt]);
            }
            {   // hi(A) x lo(B)
                uint32_t bl[4][2];
                LDSM4(bl[0][0], bl[0][1], bl[1][0], bl[1][1], bb + STG + off);
                LDSM4(bl[2][0], bl[2][1], bl[3][0], bl[3][1],
                      bb + STG + 16 * PITCH_B + off);
#pragma unroll
                for (int mt = 0; mt < 4; mt++)
#pragma unroll
                    for (int nt = 0; nt < 4; nt++)
                        MMA16816(acc[mt][nt], ah[mt], bl[nt]);
            }
        }
    }

    // ---- epilogue ----
    const int r0 = row0 + wm * 64 + (lane >> 2);
    const int c0 = col0 + wn * 32 + (lane & 3) * 2;

    if (dosm) {
        // warp's 32 columns are exactly one head group
#pragma unroll
        for (int mt = 0; mt < 4; mt++)
#pragma unroll
            for (int h = 0; h < 2; h++) {
                float mx = -1e30f;
#pragma unroll
                for (int nt = 0; nt < 4; nt++)
                    mx = fmaxf(mx, fmaxf(acc[mt][nt][2*h], acc[mt][nt][2*h+1]));
                mx = fmaxf(mx, __shfl_xor_sync(0xffffffffu, mx, 1));
                mx = fmaxf(mx, __shfl_xor_sync(0xffffffffu, mx, 2));
                float s = 0.f;
#pragma unroll
                for (int nt = 0; nt < 4; nt++) {
                    acc[mt][nt][2*h]   = __expf(acc[mt][nt][2*h]   - mx);
                    acc[mt][nt][2*h+1] = __expf(acc[mt][nt][2*h+1] - mx);
                    s += acc[mt][nt][2*h] + acc[mt][nt][2*h+1];
                }
                s += __shfl_xor_sync(0xffffffffu, s, 1);
                s += __shfl_xor_sync(0xffffffffu, s, 2);
                const float inv = 1.0f / s;
#pragma unroll
                for (int nt = 0; nt < 4; nt++) {
                    acc[mt][nt][2*h]   *= inv;
                    acc[mt][nt][2*h+1] *= inv;
                }
            }
        // write Pq as bf16 hi/lo
#pragma unroll
        for (int mt = 0; mt < 4; mt++)
#pragma unroll
            for (int nt = 0; nt < 4; nt++) {
                const int r = r0 + mt * 16, c = c0 + nt * 8;
                uint32_t h0, l0, h1, l1;
                split2(acc[mt][nt][0], acc[mt][nt][1], h0, l0);
                split2(acc[mt][nt][2], acc[mt][nt][3], h1, l1);
                *(uint32_t*)(Ph + (size_t)r * 256 + c)       = h0;
                *(uint32_t*)(Pl + (size_t)r * 256 + c)       = l0;
                *(uint32_t*)(Ph + (size_t)(r + 8) * 256 + c) = h1;
                *(uint32_t*)(Pl + (size_t)(r + 8) * 256 + c) = l1;
            }
        return;
    }

    // fp32 store (Pk / Pv / out)
#pragma unroll
    for (int mt = 0; mt < 4; mt++)
#pragma unroll
        for (int nt = 0; nt < 4; nt++) {
            const int r = r0 + mt * 16, c = c0 + nt * 8;
            *(float2*)&C[(size_t)r * 256 + c] =
                make_float2(acc[mt][nt][0], acc[mt][nt][1]);
            *(float2*)&C[(size_t)(r + 8) * 256 + c] =
                make_float2(acc[mt][nt][2], acc[mt][nt][3]);
        }

    if (dost) {
        // fused kstat pass-1 over this 128-row x 128-col block.
        float cm[8], cs[8];
#pragma unroll
        for (int nt = 0; nt < 4; nt++)
#pragma unroll
            for (int j = 0; j < 2; j++) {
                const int idx = nt * 2 + j;
                float m = -1e30f;
#pragma unroll
                for (int mt = 0; mt < 4; mt++)
                    m = fmaxf(m, fmaxf(acc[mt][nt][j], acc[mt][nt][j + 2]));
                m = fmaxf(m, __shfl_xor_sync(0xffffffffu, m, 4));
                m = fmaxf(m, __shfl_xor_sync(0xffffffffu, m, 8));
                m = fmaxf(m, __shfl_xor_sync(0xffffffffu, m, 16));
                float s = 0.f;
#pragma unroll
                for (int mt = 0; mt < 4; mt++)
                    s += __expf(acc[mt][nt][j] - m) + __expf(acc[mt][nt][j + 2] - m);
                s += __shfl_xor_sync(0xffffffffu, s, 4);
                s += __shfl_xor_sync(0xffffffffu, s, 8);
                s += __shfl_xor_sync(0xffffffffu, s, 16);
                cm[idx] = m;
                cs[idx] = s;
            }
        __syncthreads();                 // mainloop smem no longer needed
        float* fst = (float*)sm;         // [wm][wn][32 cols][2]
        if ((lane >> 2) == 0) {
#pragma unroll
            for (int idx = 0; idx < 8; idx++) {
                const int cl = (lane & 3) * 2 + (idx >> 1) * 8 + (idx & 1);
                const int o = (((wm * 4 + wn) * 32) + cl) * 2;
                fst[o]     = cm[idx];
                fst[o + 1] = cs[idx];
            }
        }
        __syncthreads();
        if (tid < 128) {
            const int wn2 = tid >> 5, cl = tid & 31;
            const float m0 = fst[((0 * 4 + wn2) * 32 + cl) * 2];
            const float s0 = fst[((0 * 4 + wn2) * 32 + cl) * 2 + 1];
            const float m1 = fst[((1 * 4 + wn2) * 32 + cl) * 2];
            const float s1 = fst[((1 * 4 + wn2) * 32 + cl) * 2 + 1];
            const float M = fmaxf(m0, m1);
            const float S = s0 * __expf(m0 - M) + s1 * __expf(m1 - M);
            pmax[(size_t)mb * 256 + col0 + wn2 * 32 + cl] = M;
            psum[(size_t)mb * 256 + col0 + wn2 * 32 + cl] = S;
        }
    }
}

// -------------------- k column stats merge (32 chunks/bf) ------------------
__global__ void __launch_bounds__(256) kstat_merge(
    const float* __restrict__ pmax, const float* __restrict__ psum,
    float* __restrict__ cmax, float* __restrict__ cinv)
{
    const int bf = blockIdx.x, t = threadIdx.x;
    float m = -1e30f;
#pragma unroll
    for (int ch = 0; ch < 32; ch++)
        m = fmaxf(m, pmax[(size_t)(bf * 32 + ch) * 256 + t]);
    float s = 0.f;
#pragma unroll
    for (int ch = 0; ch < 32; ch++) {
        const size_t o = (size_t)(bf * 32 + ch) * 256 + t;
        s += psum[o] * __expf(pmax[o] - m);
    }
    cmax[bf * 256 + t] = m;
    cinv[bf * 256 + t] = 1.0f / s;
}

// -------------------- context (32x32) + W2 fold (known-good) ---------------
__global__ void __launch_bounds__(256) ctx_w2_kernel(
    const float* __restrict__ Pk, const float* __restrict__ Pv,
    const float* __restrict__ cmax, const float* __restrict__ cinv,
    const float* __restrict__ Wo, float* __restrict__ W2)
{
    __shared__ float sk[64 * 32];
    __shared__ float sv[64 * 32];
    __shared__ float sC[32 * 32];
    __shared__ float scmax[32];

    const int bf = blockIdx.x, h = blockIdx.y;
    const int t = threadIdx.x;
    const int d = t & 31, eg = t >> 5, e0 = eg * 4;

    if (t < 32) scmax[t] = cmax[bf * 256 + h * 32 + t];
    __syncthreads();

    float acc0 = 0.f, acc1 = 0.f, acc2 = 0.f, acc3 = 0.f;
    const float* pkb = Pk + (size_t)bf * NSPA * 256 + h * 32;
    const float* pvb = Pv + (size_t)bf * NSPA * 256 + h * 32;

    for (int n0 = 0; n0 < NSPA; n0 += 64) {
#pragma unroll
        for (int i = 0; i < 2; i++) {
            const int idx = t + i * 256;
            const int rr = idx >> 3, c4 = (idx & 7) * 4;
            const float4 kv = *(const float4*)(pkb + (size_t)(n0 + rr) * 256 + c4);
            const float4 vv = *(const float4*)(pvb + (size_t)(n0 + rr) * 256 + c4);
            float4 ke;
            ke.x = __expf(kv.x - scmax[c4 + 0]);
            ke.y = __expf(kv.y - scmax[c4 + 1]);
            ke.z = __expf(kv.z - scmax[c4 + 2]);
            ke.w = __expf(kv.w - scmax[c4 + 3]);
            *(float4*)&sk[rr * 32 + c4] = ke;
            *(float4*)&sv[rr * 32 + c4] = vv;
        }
        __syncthreads();
#pragma unroll 8
        for (int nn = 0; nn < 64; nn++) {
            const float kd = sk[nn * 32 + d];
            const float4 v4 = *(const float4*)&sv[nn * 32 + e0];
            acc0 += kd * v4.x;
            acc1 += kd * v4.y;
            acc2 += kd * v4.z;
            acc3 += kd * v4.w;
        }
        __syncthreads();
    }

    const float inv = cinv[bf * 256 + h * 32 + d];
    sC[d * 32 + e0 + 0] = acc0 * inv;
    sC[d * 32 + e0 + 1] = acc1 * inv;
    sC[d * 32 + e0 + 2] = acc2 * inv;
    sC[d * 32 + e0 + 3] = acc3 * inv;
    __syncthreads();

    float wo[32];
#pragma unroll
    for (int e = 0; e < 32; e++) wo[e] = Wo[(size_t)(h * 32 + e) * 256 + t];
    float* w2p = W2 + ((size_t)bf * 256 + h * 32) * 256 + t;
    for (int d2 = 0; d2 < 32; d2++) {
        float s = 0.f;
#pragma unroll
        for (int e = 0; e < 32; e++) s += sC[d2 * 32 + e] * wo[e];
        w2p[(size_t)d2 * 256] = s;
    }
}

// ------------------------------ launcher -----------------------------------
extern "C" void kernel_launch(void* const* d_in, const int* in_sizes, int n_in,
                              void* d_out, int out_size)
{
    (void)in_sizes; (void)n_in; (void)out_size;
    const float* x  = (const float*)d_in[0];
    const float* Wq = (const float*)d_in[1];
    const float* Wk = (const float*)d_in[2];
    const float* Wv = (const float*)d_in[3];
    const float* Wo = (const float*)d_in[4];
    float* out = (float*)d_out;

    float *Pk, *Pv, *pmax, *psum, *cmax, *cinv, *W2;
    __nv_bfloat16 *Xh, *Xl, *Pqh, *Pql, *Wth, *Wtl, *W2th, *W2tl;
    cudaGetSymbolAddress((void**)&Pk,   g_Pk);
    cudaGetSymbolAddress((void**)&Pv,   g_Pv);
    cudaGetSymbolAddress((void**)&Xh,   g_Xh);
    cudaGetSymbolAddress((void**)&Xl,   g_Xl);
    cudaGetSymbolAddress((void**)&Pqh,  g_Pqh);
    cudaGetSymbolAddress((void**)&Pql,  g_Pql);
    cudaGetSymbolAddress((void**)&pmax, g_pmax);
    cudaGetSymbolAddress((void**)&psum, g_psum);
    cudaGetSymbolAddress((void**)&cmax, g_cmax);
    cudaGetSymbolAddress((void**)&cinv, g_cinv);
    cudaGetSymbolAddress((void**)&W2,   g_W2);
    cudaGetSymbolAddress((void**)&Wth,  g_Wt_hi);
    cudaGetSymbolAddress((void**)&Wtl,  g_Wt_lo);
    cudaGetSymbolAddress((void**)&W2th, g_W2t_hi);
    cudaGetSymbolAddress((void**)&W2tl, g_W2t_lo);

    cudaFuncSetAttribute(mma_gemm, cudaFuncAttributeMaxDynamicSharedMemorySize,
                         SMEM_TOTAL);

    xsplit<<<MROWS * 256 / 1024, 256>>>(x, Xh, Xl);

    const dim3 tb(32, 8);
    tsplit<<<dim3(8, 8, 1), tb>>>(Wq, Wth,          Wtl);
    tsplit<<<dim3(8, 8, 1), tb>>>(Wk, Wth + 65536,  Wtl + 65536);
    tsplit<<<dim3(8, 8, 1), tb>>>(Wv, Wth + 131072, Wtl + 131072);

    // projections: Pq (softmax -> bf16 hi/lo), Pk (fp32 + stats), Pv (fp32)
    mma_gemm<<<dim3(3, 2048), 256, SMEM_TOTAL>>>(
        Xh, Xl, Wth, Wtl, nullptr, Pk, Pv, Pqh, Pql, pmax, psum, 0, 1);

    kstat_merge<<<BFU, 256>>>(pmax, psum, cmax, cinv);
    ctx_w2_kernel<<<dim3(BFU, HEADS), 256>>>(Pk, Pv, cmax, cinv, Wo, W2);

    tsplit<<<dim3(8, 8, BFU), tb>>>(W2, W2th, W2tl);

    // out = Pq @ W2[bf]
    mma_gemm<<<dim3(1, 2048), 256, SMEM_TOTAL>>>(
        Pqh, Pql, W2th, W2tl, out, nullptr, nullptr, nullptr, nullptr,
        nullptr, nullptr, 1, 0);
}